// round 13
// baseline (speedup 1.0000x reference)
#include <cuda_runtime.h>
#include <math.h>

#define BATCH   16
#define NPTS    4096
#define NPNT    1024
#define NSAMP   32
#define PIX     (NSAMP*NPNT)      // 32768 pixels per batch
#define CIN0    67

typedef unsigned long long u64;
__device__ __forceinline__ u64 pk2(float lo, float hi) {
    u64 r; asm("mov.b64 %0,{%1,%2};" : "=l"(r) : "f"(lo), "f"(hi)); return r;
}
__device__ __forceinline__ void upk2(u64 v, float& lo, float& hi) {
    asm("mov.b64 {%0,%1},%2;" : "=f"(lo), "=f"(hi) : "l"(v));
}
__device__ __forceinline__ void ffma2(u64& d, u64 a, u64 b) {
    asm("fma.rn.f32x2 %0,%1,%2,%0;" : "+l"(d) : "l"(a), "l"(b));
}
__device__ __forceinline__ u64 add2(u64 a, u64 b) {
    u64 r; asm("add.rn.f32x2 %0,%1,%2;" : "=l"(r) : "l"(a), "l"(b)); return r;
}
__device__ __forceinline__ u64 mul2(u64 a, u64 b) {
    u64 r; asm("mul.rn.f32x2 %0,%1,%2;" : "=l"(r) : "l"(a), "l"(b)); return r;
}

// ---------------- device scratch (static: no allocs allowed) ----------------
__device__ int    g_grp[BATCH*NPNT*NSAMP];
__device__ float  g_new[BATCH*NPNT*3];
__device__ float  g_A0 [BATCH*NPTS*64];
__device__ float  g_C0 [BATCH*NPNT*64];
__device__ float  g_x0 [(size_t)BATCH*64 *PIX];
__device__ float  g_x1 [(size_t)BATCH*64 *PIX];
__device__ float  g_max[(size_t)BATCH*128*NPNT];
__device__ float  g_W2d[64*256];                 // W2 pre-duplicated [ci][2*co{dup}]
// 256B-strided accumulators: channels spread across L2 slices
__device__ double g_sumP[3][128][32];
__device__ double g_sqsP[3][128][32];
__device__ float  g_bna[3][128];
__device__ float  g_bnc[3][128];

__global__ void zero_stats_kernel() {
    int i = threadIdx.x;
    if (i < 384) {
        const int l = i >> 7, c = i & 127;
        g_sumP[l][c][0] = 0.0;
        g_sqsP[l][c][0] = 0.0;
    }
}

// ---------------- W2 duplication (profiler slot filler) ----------------
__global__ void __launch_bounds__(256)
dupw2_kernel(const float* __restrict__ W)
{
    const int i = blockIdx.x*256 + threadIdx.x;    // 8192 = 128*64
    const int co = i >> 6, ci = i & 63;
    const float v = W[i];
    g_W2d[ci*256 + 2*co]     = v;
    g_W2d[ci*256 + 2*co + 1] = v;
}

// ---------------- FPS: r11 shape (256 thr, 1 batch/CTA) + lean argmax ----------------
__global__ void __launch_bounds__(256, 1)
fps_kernel(const float* __restrict__ xyz, float* __restrict__ out)
{
    extern __shared__ float sm[];
    float* sx = sm;                              // 4096
    float* sy = sm + NPTS;
    float* sz = sm + 2*NPTS;
    int*   sfi = (int*)(sm + 3*NPTS);            // 1024 selected indices
    __shared__ u64 part[2][8];

    const int b = blockIdx.x, t = threadIdx.x;
    const int lane = t & 31, wid = t >> 5;
    const unsigned FULL = 0xffffffffu;
    const float* base = xyz + (size_t)b*3*NPTS;
    for (int n = t; n < NPTS; n += 256) {
        sx[n] = base[n];
        sy[n] = base[NPTS + n];
        sz[n] = base[2*NPTS + n];
    }
    __syncthreads();

    // thread t owns pairs p = t + j*256 (points 2p, 2p+1) — coords in registers
    u64 xp[8], yp[8], zp[8];
    #pragma unroll
    for (int j = 0; j < 8; j++) {
        const int p = t + j*256;
        xp[j] = pk2(sx[2*p], sx[2*p+1]);
        yp[j] = pk2(sy[2*p], sy[2*p+1]);
        zp[j] = pk2(sz[2*p], sz[2*p+1]);
    }
    float d[16];
    #pragma unroll
    for (int r = 0; r < 16; r++) d[r] = 1e10f;

    int far = 0;
    for (int i = 0; i < NPNT; i++) {
        const float cx = sx[far], cy = sy[far], cz = sz[far];
        const u64 ncx = pk2(-cx, -cx), ncy = pk2(-cy, -cy), ncz = pk2(-cz, -cz);
        if (t == 0) sfi[i] = far;

        float bv = -1.0f;
        #pragma unroll
        for (int j = 0; j < 8; j++) {
            // per-lane identical to __fsub_rn/__fmul_rn/__fadd_rn, left-assoc sum
            const u64 dx = add2(xp[j], ncx);
            const u64 dy = add2(yp[j], ncy);
            const u64 dz = add2(zp[j], ncz);
            const u64 dd = add2(add2(mul2(dx, dx), mul2(dy, dy)), mul2(dz, dz));
            float f0, f1; upk2(dd, f0, f1);
            d[2*j]   = fminf(d[2*j],   f0);
            d[2*j+1] = fminf(d[2*j+1], f1);
            bv = fmaxf(bv, d[2*j]);
            bv = fmaxf(bv, d[2*j+1]);
        }
        // warp argmax: max of float bits (monotone, bv>=0); index recovered by the
        // (rare) winning lane via descending equality scan -> lowest index among ties
        const unsigned bits = __float_as_uint(bv);
        const unsigned mx   = __reduce_max_sync(FULL, bits);
        int cand = 0x7fffffff;
        if (bits == mx) {
            #pragma unroll
            for (int e = 15; e >= 0; e--) {
                const int n = 2*(t + (e >> 1)*256) + (e & 1);
                if (d[e] == bv) cand = n;
            }
        }
        const int wmin = __reduce_min_sync(FULL, cand);
        if (lane == 0) part[i & 1][wid] = ((u64)__float_as_uint(bv == __uint_as_float(0) ? 0.f : __uint_as_float(mx)) << 32) | (unsigned)wmin;
        __syncthreads();
        const u64 v = part[i & 1][lane & 7];
        const unsigned pb = (unsigned)(v >> 32);
        const unsigned m2 = __reduce_max_sync(FULL, pb);
        const int c2 = (pb == m2) ? (int)(unsigned)(v & 0xffffffffu) : 0x7fffffff;
        far = __reduce_min_sync(FULL, c2);
    }
    __syncthreads();
    for (int i = t; i < NPNT; i += 256) {
        const int f = sfi[i];
        const float cx = sx[f], cy = sy[f], cz = sz[f];
        g_new[(b*NPNT + i)*3 + 0] = cx;
        g_new[(b*NPNT + i)*3 + 1] = cy;
        g_new[(b*NPNT + i)*3 + 2] = cz;
        out[b*3*NPNT            + i] = cx;
        out[b*3*NPNT +   NPNT   + i] = cy;
        out[b*3*NPNT + 2*NPNT   + i] = cz;
    }
}

// ---------------- ball query (UNCHANGED — passing arithmetic) ----------------
__global__ void __launch_bounds__(256)
ball_kernel(const float* __restrict__ xyz)
{
    const int w    = (blockIdx.x*blockDim.x + threadIdx.x) >> 5;
    const int lane = threadIdx.x & 31;
    const int b = w / NPNT, s = w % NPNT;

    const float cx = g_new[(b*NPNT + s)*3 + 0];
    const float cy = g_new[(b*NPNT + s)*3 + 1];
    const float cz = g_new[(b*NPNT + s)*3 + 2];
    const float ns = cx*cx + cy*cy + cz*cz;
    const float R2 = 0.01f;

    const float* px = xyz + (size_t)b*3*NPTS;
    int cnt = 0, first = 0;
    int* grp = g_grp + (b*NPNT + s)*NSAMP;

    for (int bs = 0; bs < NPTS; bs += 32) {
        const int n = bs + lane;
        const float xx = px[n], xy = px[NPTS + n], xz = px[2*NPTS + n];
        const float dot = cx*xx + cy*xy + cz*xz;
        const float nx  = xx*xx + xy*xy + xz*xz;
        const float d   = -2.0f*dot + ns + nx;
        const bool ok = !(d > R2);
        const unsigned m = __ballot_sync(0xffffffffu, ok);
        if (m) {
            if (cnt == 0) first = bs + __ffs(m) - 1;
            const int pos = cnt + __popc(m & ((1u << lane) - 1u));
            if (ok && pos < NSAMP) grp[pos] = n;
            cnt += __popc(m);
            if (cnt >= NSAMP) break;
        }
    }
    cnt = min(cnt, NSAMP);
    for (int k = cnt + lane; k < NSAMP; k += 32) grp[k] = first;
}

// ---------------- per-point layer0 partial (UNCHANGED) ----------------
__global__ void __launch_bounds__(256)
a0_kernel(const float* __restrict__ xyz, const float* __restrict__ pts,
          const float* __restrict__ W0, const float* __restrict__ b0)
{
    __shared__ float sWt[CIN0*64];      // [j][co]
    __shared__ float sB[64];
    const int b = blockIdx.y;
    const int n = blockIdx.x*256 + threadIdx.x;
    for (int i = threadIdx.x; i < 64*CIN0; i += 256) {
        const int co = i / CIN0, j = i - co*CIN0;
        sWt[j*64 + co] = W0[i];
    }
    for (int i = threadIdx.x; i < 64; i += 256) sB[i] = b0[i];
    __syncthreads();

    float f[CIN0];
    const float* xb = xyz + (size_t)b*3*NPTS;
    f[0] = xb[n]; f[1] = xb[NPTS + n]; f[2] = xb[2*NPTS + n];
    const float* pb = pts + (size_t)b*64*NPTS;
    #pragma unroll
    for (int j = 0; j < 64; j++) f[3 + j] = pb[(size_t)j*NPTS + n];

    float* outp = g_A0 + ((size_t)b*NPTS + n)*64;
    #pragma unroll 1
    for (int c8 = 0; c8 < 64; c8 += 8) {
        u64 acc[4];
        #pragma unroll
        for (int r = 0; r < 4; r++) acc[r] = pk2(sB[c8 + 2*r], sB[c8 + 2*r + 1]);
        #pragma unroll
        for (int j = 0; j < CIN0; j++) {
            const u64 fd = pk2(f[j], f[j]);
            const ulonglong2 wa = *reinterpret_cast<const ulonglong2*>(sWt + j*64 + c8);
            const ulonglong2 wb = *reinterpret_cast<const ulonglong2*>(sWt + j*64 + c8 + 4);
            ffma2(acc[0], wa.x, fd);
            ffma2(acc[1], wa.y, fd);
            ffma2(acc[2], wb.x, fd);
            ffma2(acc[3], wb.y, fd);
        }
        float v0,v1,v2,v3,v4,v5,v6,v7;
        upk2(acc[0], v0, v1); upk2(acc[1], v2, v3);
        upk2(acc[2], v4, v5); upk2(acc[3], v6, v7);
        *reinterpret_cast<float4*>(outp + c8)     = make_float4(v0, v1, v2, v3);
        *reinterpret_cast<float4*>(outp + c8 + 4) = make_float4(v4, v5, v6, v7);
    }
}

// ---------------- per-centroid layer0 partial (UNCHANGED) ----------------
__global__ void __launch_bounds__(256)
c0_kernel(const float* __restrict__ W0)
{
    __shared__ float sw[192];
    const int b = blockIdx.y;
    const int s = blockIdx.x*256 + threadIdx.x;
    for (int i = threadIdx.x; i < 192; i += 256) sw[i] = W0[(i/3)*CIN0 + (i%3)];
    __syncthreads();

    const float x = g_new[(b*NPNT + s)*3 + 0];
    const float y = g_new[(b*NPNT + s)*3 + 1];
    const float z = g_new[(b*NPNT + s)*3 + 2];
    float* outp = g_C0 + ((size_t)b*NPNT + s)*64;
    #pragma unroll 1
    for (int c4 = 0; c4 < 64; c4 += 4) {
        float4 o;
        o.x = sw[(c4+0)*3]*x + sw[(c4+0)*3+1]*y + sw[(c4+0)*3+2]*z;
        o.y = sw[(c4+1)*3]*x + sw[(c4+1)*3+1]*y + sw[(c4+1)*3+2]*z;
        o.z = sw[(c4+2)*3]*x + sw[(c4+2)*3+1]*y + sw[(c4+2)*3+2]*z;
        o.w = sw[(c4+3)*3]*x + sw[(c4+3)*3+1]*y + sw[(c4+3)*3+2]*z;
        *reinterpret_cast<float4*>(outp + c4) = o;
    }
}

// ---------------- k0s: gather x0 = A0[idx]-C0[s], write + fused BN0 stats ----------------
__global__ void __launch_bounds__(256)
k0s_kernel()
{
    extern __shared__ float smk[];
    float* tile = smk;                            // [64][260]  (66,560 B)
    int*   sidx = (int*)(smk + 64*260);           // 256 idx
    __shared__ float ps[256], pq[256];

    const int b  = blockIdx.y;
    const int p0 = blockIdx.x * 256;              // 256 pixels, same k
    const int k  = p0 >> 10, s0 = p0 & 1023;
    const int tid = threadIdx.x;

    sidx[tid] = g_grp[(b*NPNT + s0 + tid)*NSAMP + k];
    __syncthreads();

    {
        const int idx = sidx[tid];
        const float4* A = (const float4*)(g_A0 + ((size_t)b*NPTS + idx    )*64);
        const float4* C = (const float4*)(g_C0 + ((size_t)b*NPNT + s0+tid )*64);
        #pragma unroll
        for (int u = 0; u < 16; u++) {
            const float4 a  = A[u];
            const float4 c4 = C[u];
            const int c = u*4;
            tile[(c+0)*260 + tid] = a.x - c4.x;
            tile[(c+1)*260 + tid] = a.y - c4.y;
            tile[(c+2)*260 + tid] = a.z - c4.z;
            tile[(c+3)*260 + tid] = a.w - c4.w;
        }
    }
    __syncthreads();

    {
        float* outb = g_x0 + (size_t)b*64*PIX + p0 + tid;
        #pragma unroll 8
        for (int c = 0; c < 64; c++) outb[(size_t)c*PIX] = tile[c*260 + tid];
    }

    {
        const int c = tid & 63, g = tid >> 6;
        const float* row = tile + c*260 + g*64;
        float s = 0.f, q = 0.f;
        #pragma unroll 16
        for (int j = 0; j < 64; j++) { const float v = row[j]; s += v; q = fmaf(v, v, q); }
        ps[tid] = s; pq[tid] = q;
    }
    __syncthreads();
    if (tid < 64) {
        const float S = ((ps[tid] + ps[tid+64]) + ps[tid+128]) + ps[tid+192];
        const float Q = ((pq[tid] + pq[tid+64]) + pq[tid+128]) + pq[tid+192];
        atomicAdd(&g_sumP[0][tid][0], (double)S);
        atomicAdd(&g_sqsP[0][tid][0], (double)Q);
    }
}

// ---------------- fold BN ----------------
__global__ void finalize_kernel(int layer, int C,
                                const float* __restrict__ gamma,
                                const float* __restrict__ beta)
{
    const int c = threadIdx.x;
    if (c >= C) return;
    const double n = (double)BATCH * PIX;
    const double mean = g_sumP[layer][c][0] / n;
    double var = g_sqsP[layer][c][0] / n - mean*mean;
    if (var < 0.0) var = 0.0;
    const float inv = (float)(1.0 / sqrt(var + 1e-5));
    const float a = gamma[c] * inv;
    g_bna[layer][c] = a;
    g_bnc[layer][c] = beta[c] - (float)mean * a;
}

// ---------------- gemm1 (UNCHANGED from r12) ----------------
__global__ void __launch_bounds__(256)
gemm1_kernel(const float* __restrict__ W, const float* __restrict__ bias)
{
    extern __shared__ float smem[];
    float* Xs = smem;                   // 64 x 128
    float* Wd = Xs + 64*128;            // 64 x 128 (dup pairs per co)
    float* sa = Wd + 64*128;
    float* sc = sa + 64;
    float* sb = sc + 64;

    const int b = blockIdx.y;
    const int pbase = blockIdx.x * 128;
    const int tid = threadIdx.x;

    for (int i = tid; i < 64; i += 256) { sa[i] = g_bna[0][i]; sc[i] = g_bnc[0][i]; sb[i] = bias[i]; }
    for (int i = tid; i < 64*64; i += 256) {
        const int co = i >> 6, ci = i & 63;
        const float v = W[i];
        Wd[ci*128 + 2*co]     = v;
        Wd[ci*128 + 2*co + 1] = v;
    }
    __syncthreads();

    const float* xb = g_x0 + (size_t)b*64*PIX + pbase;
    for (int i = tid; i < 64*128; i += 256) {
        const int ci = i >> 7, pp = i & 127;
        Xs[i] = fmaxf(fmaf(xb[(size_t)ci*PIX + pp], sa[ci], sc[ci]), 0.0f);
    }
    __syncthreads();

    const int p0 = (tid & 31) << 2;
    const int c0 = (tid >> 5) << 3;
    u64 acc[8][2];
    #pragma unroll
    for (int r = 0; r < 8; r++) { acc[r][0] = 0ull; acc[r][1] = 0ull; }

    #pragma unroll 8
    for (int ci = 0; ci < 64; ci++) {
        const ulonglong2 xv = *reinterpret_cast<const ulonglong2*>(Xs + (ci << 7) + p0);
        const ulonglong2* wp = reinterpret_cast<const ulonglong2*>(Wd + (ci << 7) + (c0 << 1));
        const ulonglong2 w0 = wp[0], w1 = wp[1], w2 = wp[2], w3 = wp[3];
        ffma2(acc[0][0], w0.x, xv.x); ffma2(acc[0][1], w0.x, xv.y);
        ffma2(acc[1][0], w0.y, xv.x); ffma2(acc[1][1], w0.y, xv.y);
        ffma2(acc[2][0], w1.x, xv.x); ffma2(acc[2][1], w1.x, xv.y);
        ffma2(acc[3][0], w1.y, xv.x); ffma2(acc[3][1], w1.y, xv.y);
        ffma2(acc[4][0], w2.x, xv.x); ffma2(acc[4][1], w2.x, xv.y);
        ffma2(acc[5][0], w2.y, xv.x); ffma2(acc[5][1], w2.y, xv.y);
        ffma2(acc[6][0], w3.x, xv.x); ffma2(acc[6][1], w3.x, xv.y);
        ffma2(acc[7][0], w3.y, xv.x); ffma2(acc[7][1], w3.y, xv.y);
    }

    float ss[8], qq[8];
    #pragma unroll
    for (int r = 0; r < 8; r++) {
        float v0, v1, v2, v3;
        upk2(acc[r][0], v0, v1);
        upk2(acc[r][1], v2, v3);
        const float bb = sb[c0 + r];
        v0 += bb; v1 += bb; v2 += bb; v3 += bb;
        *reinterpret_cast<float4*>(g_x1 + ((size_t)(b*64 + c0 + r))*PIX + pbase + p0)
            = make_float4(v0, v1, v2, v3);
        ss[r] = ((v0 + v1) + v2) + v3;
        qq[r] = fmaf(v3, v3, fmaf(v2, v2, fmaf(v1, v1, v0*v0)));
    }
    const unsigned FULL = 0xffffffffu;
    #pragma unroll
    for (int r = 0; r < 8; r++) {
        #pragma unroll
        for (int o = 16; o; o >>= 1) {
            ss[r] += __shfl_xor_sync(FULL, ss[r], o);
            qq[r] += __shfl_xor_sync(FULL, qq[r], o);
        }
    }
    if ((tid & 31) == 0) {
        #pragma unroll
        for (int r = 0; r < 8; r++) {
            atomicAdd(&g_sumP[1][c0 + r][0], (double)ss[r]);
            atomicAdd(&g_sqsP[1][c0 + r][0], (double)qq[r]);
        }
    }
}

// ---------------- gemm2 (UNCHANGED from r12) ----------------
__global__ void __launch_bounds__(512)
gemm2_kernel(const float* __restrict__ bias)
{
    extern __shared__ float smem[];
    float* Xs = smem;                   // 64 x 64
    float* Wd = Xs + 64*64;             // 64 x 256 (dup pairs per co)
    float* sa = Wd + 64*256;
    float* sc = sa + 64;
    float* sb = sc + 64;                // 128

    const int b  = blockIdx.y;
    const int s0 = blockIdx.x * 64;
    const int tid = threadIdx.x;

    for (int i = tid; i < 64;  i += 512) { sa[i] = g_bna[1][i]; sc[i] = g_bnc[1][i]; }
    for (int i = tid; i < 128; i += 512) sb[i] = bias[i];
    {
        const float4* src = (const float4*)g_W2d;
        float4* dst = (float4*)Wd;
        for (int i = tid; i < 64*256/4; i += 512) dst[i] = src[i];
    }

    const int pcol = (tid & 15) << 2;   // 4 pixels
    const int c0   = (tid >> 4) << 2;   // 4 channels
    float rmax[4][4];
    float ss[4], qq[4];
    #pragma unroll
    for (int r = 0; r < 4; r++) {
        ss[r] = 0.f; qq[r] = 0.f;
        rmax[r][0] = -3.4e38f; rmax[r][1] = -3.4e38f; rmax[r][2] = -3.4e38f; rmax[r][3] = -3.4e38f;
    }

    const float* xb = g_x1 + (size_t)b*64*PIX + s0;
    float st[8];
    #pragma unroll
    for (int j = 0; j < 8; j++) {
        const int i = tid + j*512;
        st[j] = xb[(size_t)(i >> 6)*PIX + (i & 63)];
    }

    for (int k = 0; k < NSAMP; k++) {
        __syncthreads();
        #pragma unroll
        for (int j = 0; j < 8; j++) {
            const int i = tid + j*512;
            const int ci = i >> 6;
            Xs[i] = fmaxf(fmaf(st[j], sa[ci], sc[ci]), 0.0f);
        }
        __syncthreads();
        if (k + 1 < NSAMP) {
            const float* xk = xb + (k+1)*NPNT;
            #pragma unroll
            for (int j = 0; j < 8; j++) {
                const int i = tid + j*512;
                st[j] = xk[(size_t)(i >> 6)*PIX + (i & 63)];
            }
        }

        u64 acc[4][2];
        #pragma unroll
        for (int r = 0; r < 4; r++) { acc[r][0] = 0ull; acc[r][1] = 0ull; }

        #pragma unroll 8
        for (int ci = 0; ci < 64; ci++) {
            const ulonglong2 xv = *reinterpret_cast<const ulonglong2*>(Xs + (ci << 6) + pcol);
            const ulonglong2* wp = reinterpret_cast<const ulonglong2*>(Wd + (ci << 8) + (c0 << 1));
            const ulonglong2 w0 = wp[0], w1 = wp[1];
            ffma2(acc[0][0], w0.x, xv.x); ffma2(acc[0][1], w0.x, xv.y);
            ffma2(acc[1][0], w0.y, xv.x); ffma2(acc[1][1], w0.y, xv.y);
            ffma2(acc[2][0], w1.x, xv.x); ffma2(acc[2][1], w1.x, xv.y);
            ffma2(acc[3][0], w1.y, xv.x); ffma2(acc[3][1], w1.y, xv.y);
        }

        #pragma unroll
        for (int r = 0; r < 4; r++) {
            float v0, v1, v2, v3;
            upk2(acc[r][0], v0, v1);
            upk2(acc[r][1], v2, v3);
            const float bb = sb[c0 + r];
            v0 += bb; v1 += bb; v2 += bb; v3 += bb;
            rmax[r][0] = fmaxf(rmax[r][0], v0);
            rmax[r][1] = fmaxf(rmax[r][1], v1);
            rmax[r][2] = fmaxf(rmax[r][2], v2);
            rmax[r][3] = fmaxf(rmax[r][3], v3);
            ss[r] += v0; qq[r] = fmaf(v0, v0, qq[r]);
            ss[r] += v1; qq[r] = fmaf(v1, v1, qq[r]);
            ss[r] += v2; qq[r] = fmaf(v2, v2, qq[r]);
            ss[r] += v3; qq[r] = fmaf(v3, v3, qq[r]);
        }
    }

    #pragma unroll
    for (int r = 0; r < 4; r++) {
        *reinterpret_cast<float4*>(g_max + (((size_t)(b*128 + c0 + r)) << 10) + s0 + pcol)
            = make_float4(rmax[r][0], rmax[r][1], rmax[r][2], rmax[r][3]);
    }
    const unsigned FULL = 0xffffffffu;
    #pragma unroll
    for (int r = 0; r < 4; r++) {
        #pragma unroll
        for (int o = 8; o; o >>= 1) {
            ss[r] += __shfl_xor_sync(FULL, ss[r], o);
            qq[r] += __shfl_xor_sync(FULL, qq[r], o);
        }
    }
    if ((tid & 15) == 0) {
        #pragma unroll
        for (int r = 0; r < 4; r++) {
            atomicAdd(&g_sumP[2][c0 + r][0], (double)ss[r]);
            atomicAdd(&g_sqsP[2][c0 + r][0], (double)qq[r]);
        }
    }
}

// ---------------- apply BN2+relu to the raw max ----------------
__global__ void __launch_bounds__(256)
maxapply_kernel(float* __restrict__ out)
{
    const int idx = blockIdx.x*256 + threadIdx.x;
    const int co  = (idx >> 10) & 127;
    const float v = g_max[idx];
    out[BATCH*3*NPNT + idx] = fmaxf(fmaf(v, g_bna[2][co], g_bnc[2][co]), 0.0f);
}

// ---------------- launcher ----------------
extern "C" void kernel_launch(void* const* d_in, const int* in_sizes, int n_in,
                              void* d_out, int out_size)
{
    const float* xyz = (const float*)d_in[0];
    const float* pts = (const float*)d_in[1];
    const float* W0  = (const float*)d_in[2];
    const float* b0  = (const float*)d_in[3];
    const float* ga0 = (const float*)d_in[4];
    const float* be0 = (const float*)d_in[5];
    const float* W1  = (const float*)d_in[6];
    const float* b1  = (const float*)d_in[7];
    const float* ga1 = (const float*)d_in[8];
    const float* be1 = (const float*)d_in[9];
    const float* W2  = (const float*)d_in[10];
    const float* b2  = (const float*)d_in[11];
    const float* ga2 = (const float*)d_in[12];
    const float* be2 = (const float*)d_in[13];
    float* out = (float*)d_out;

    const int FPS_SMEM = (3*NPTS)*4 + NPNT*4;              // 53,248
    const int K0_SMEM  = (64*260)*4 + 256*4;               // 67,584
    const int SM1 = (64*128 + 64*128 + 64+64+64 ) * 4;     // 66,304
    const int SM2 = (64*64  + 64*256 + 64+64+128) * 4;     // 82,944
    cudaFuncSetAttribute((const void*)fps_kernel,   cudaFuncAttributeMaxDynamicSharedMemorySize, FPS_SMEM);
    cudaFuncSetAttribute((const void*)k0s_kernel,   cudaFuncAttributeMaxDynamicSharedMemorySize, K0_SMEM);
    cudaFuncSetAttribute((const void*)gemm1_kernel, cudaFuncAttributeMaxDynamicSharedMemorySize, SM1);
    cudaFuncSetAttribute((const void*)gemm2_kernel, cudaFuncAttributeMaxDynamicSharedMemorySize, SM2);

    // order keeps fps in the profiler's 4th-launch capture slot
    zero_stats_kernel<<<1, 384>>>();
    a0_kernel  <<<dim3(NPTS/256, BATCH), 256>>>(xyz, pts, W0, b0);
    dupw2_kernel<<<32, 256>>>(W2);
    fps_kernel <<<BATCH, 256, FPS_SMEM>>>(xyz, out);
    ball_kernel<<<(BATCH*NPNT*32)/256, 256>>>(xyz);
    c0_kernel  <<<dim3(NPNT/256, BATCH), 256>>>(W0);
    k0s_kernel <<<dim3(PIX/256, BATCH), 256, K0_SMEM>>>();

    finalize_kernel<<<1, 128>>>(0, 64, ga0, be0);
    gemm1_kernel   <<<dim3(PIX/128, BATCH), 256, SM1>>>(W1, b1);

    finalize_kernel<<<1, 128>>>(1, 64, ga1, be1);
    gemm2_kernel   <<<dim3(NPNT/64, BATCH), 512, SM2>>>(b2);

    finalize_kernel<<<1, 128>>>(2, 128, ga2, be2);
    maxapply_kernel<<<(BATCH*128*NPNT)/256, 256>>>(out);
}

// round 14
// speedup vs baseline: 1.6404x; 1.6404x over previous
#include <cuda_runtime.h>
#include <math.h>

#define BATCH   16
#define NPTS    4096
#define NPNT    1024
#define NSAMP   32
#define PIX     (NSAMP*NPNT)      // 32768 pixels per batch
#define CIN0    67

typedef unsigned long long u64;
__device__ __forceinline__ u64 pk2(float lo, float hi) {
    u64 r; asm("mov.b64 %0,{%1,%2};" : "=l"(r) : "f"(lo), "f"(hi)); return r;
}
__device__ __forceinline__ void upk2(u64 v, float& lo, float& hi) {
    asm("mov.b64 {%0,%1},%2;" : "=f"(lo), "=f"(hi) : "l"(v));
}
__device__ __forceinline__ void ffma2(u64& d, u64 a, u64 b) {
    asm("fma.rn.f32x2 %0,%1,%2,%0;" : "+l"(d) : "l"(a), "l"(b));
}
__device__ __forceinline__ u64 add2(u64 a, u64 b) {
    u64 r; asm("add.rn.f32x2 %0,%1,%2;" : "=l"(r) : "l"(a), "l"(b)); return r;
}
__device__ __forceinline__ u64 mul2(u64 a, u64 b) {
    u64 r; asm("mul.rn.f32x2 %0,%1,%2;" : "=l"(r) : "l"(a), "l"(b)); return r;
}

// ---------------- device scratch (static: no allocs allowed) ----------------
__device__ int    g_grp[BATCH*NPNT*NSAMP];
__device__ float  g_new[BATCH*NPNT*3];
__device__ float  g_A0 [BATCH*NPTS*64];
__device__ float  g_C0 [BATCH*NPNT*64];
__device__ float  g_x0 [(size_t)BATCH*64 *PIX];
__device__ float  g_x1 [(size_t)BATCH*64 *PIX];
__device__ float  g_max[(size_t)BATCH*128*NPNT];
__device__ float  g_W2d[64*256];                 // W2 pre-duplicated [ci][2*co{dup}]
// 256B-strided accumulators: channels spread across L2 slices
__device__ double g_sumP[3][128][32];
__device__ double g_sqsP[3][128][32];
__device__ float  g_bna[3][128];
__device__ float  g_bnc[3][128];

__global__ void zero_stats_kernel() {
    int i = threadIdx.x;
    if (i < 384) {
        const int l = i >> 7, c = i & 127;
        g_sumP[l][c][0] = 0.0;
        g_sqsP[l][c][0] = 0.0;
    }
}

// ---------------- W2 duplication (profiler slot filler) ----------------
__global__ void __launch_bounds__(256)
dupw2_kernel(const float* __restrict__ W)
{
    const int i = blockIdx.x*256 + threadIdx.x;    // 8192 = 128*64
    const int co = i >> 6, ci = i & 63;
    const float v = W[i];
    g_W2d[ci*256 + 2*co]     = v;
    g_W2d[ci*256 + 2*co + 1] = v;
}

// ---------------- FPS: EXACT r11 kernel (measured 273.9us) ----------------
__global__ void __launch_bounds__(256, 1)
fps_kernel(const float* __restrict__ xyz, float* __restrict__ out)
{
    extern __shared__ float sm[];
    float* sx = sm;                              // 4096
    float* sy = sm + NPTS;
    float* sz = sm + 2*NPTS;
    int*   sfi = (int*)(sm + 3*NPTS);            // 1024 selected indices
    __shared__ u64 part[2][8];

    const int b = blockIdx.x, t = threadIdx.x;
    const int lane = t & 31, wid = t >> 5;
    const unsigned FULL = 0xffffffffu;
    const float* base = xyz + (size_t)b*3*NPTS;
    for (int n = t; n < NPTS; n += 256) {
        sx[n] = base[n];
        sy[n] = base[NPTS + n];
        sz[n] = base[2*NPTS + n];
    }
    __syncthreads();

    // thread t owns pairs p = t + j*256 (points 2p, 2p+1) — coords in registers
    u64 xp[8], yp[8], zp[8];
    #pragma unroll
    for (int j = 0; j < 8; j++) {
        const int p = t + j*256;
        xp[j] = pk2(sx[2*p], sx[2*p+1]);
        yp[j] = pk2(sy[2*p], sy[2*p+1]);
        zp[j] = pk2(sz[2*p], sz[2*p+1]);
    }
    float d[16];
    #pragma unroll
    for (int r = 0; r < 16; r++) d[r] = 1e10f;

    int far = 0;
    for (int i = 0; i < NPNT; i++) {
        const float cx = sx[far], cy = sy[far], cz = sz[far];
        const u64 ncx = pk2(-cx, -cx), ncy = pk2(-cy, -cy), ncz = pk2(-cz, -cz);
        if (t == 0) sfi[i] = far;

        float bv = -1.0f; int bi = 0;
        #pragma unroll
        for (int j = 0; j < 8; j++) {
            // per-lane identical to __fsub_rn/__fmul_rn/__fadd_rn, left-assoc sum
            const u64 dx = add2(xp[j], ncx);
            const u64 dy = add2(yp[j], ncy);
            const u64 dz = add2(zp[j], ncz);
            const u64 dd = add2(add2(mul2(dx, dx), mul2(dy, dy)), mul2(dz, dz));
            float f0, f1; upk2(dd, f0, f1);
            const int n0 = 2*(t + j*256);
            float& a0 = d[2*j];
            float& a1 = d[2*j + 1];
            a0 = fminf(a0, f0); if (a0 > bv) { bv = a0; bi = n0; }
            a1 = fminf(a1, f1); if (a1 > bv) { bv = a1; bi = n0 + 1; }
        }
        // warp argmax: max float bits (monotone, bv>=0), min index among ties
        const unsigned bits = __float_as_uint(bv);
        const unsigned mx   = __reduce_max_sync(FULL, bits);
        const int cand      = (bits == mx) ? bi : 0x7fffffff;
        const int wmin      = __reduce_min_sync(FULL, cand);
        if (lane == 0) part[i & 1][wid] = ((u64)mx << 32) | (unsigned)wmin;
        __syncthreads();
        const u64 v = part[i & 1][lane & 7];     // 8 entries, lanes duplicate
        const unsigned pb = (unsigned)(v >> 32);
        const unsigned m2 = __reduce_max_sync(FULL, pb);
        const int c2 = (pb == m2) ? (int)(unsigned)(v & 0xffffffffu) : 0x7fffffff;
        far = __reduce_min_sync(FULL, c2);
    }
    __syncthreads();
    for (int i = t; i < NPNT; i += 256) {
        const int f = sfi[i];
        const float cx = sx[f], cy = sy[f], cz = sz[f];
        g_new[(b*NPNT + i)*3 + 0] = cx;
        g_new[(b*NPNT + i)*3 + 1] = cy;
        g_new[(b*NPNT + i)*3 + 2] = cz;
        out[b*3*NPNT            + i] = cx;
        out[b*3*NPNT +   NPNT   + i] = cy;
        out[b*3*NPNT + 2*NPNT   + i] = cz;
    }
}

// ---------------- ball query (UNCHANGED — passing arithmetic) ----------------
__global__ void __launch_bounds__(256)
ball_kernel(const float* __restrict__ xyz)
{
    const int w    = (blockIdx.x*blockDim.x + threadIdx.x) >> 5;
    const int lane = threadIdx.x & 31;
    const int b = w / NPNT, s = w % NPNT;

    const float cx = g_new[(b*NPNT + s)*3 + 0];
    const float cy = g_new[(b*NPNT + s)*3 + 1];
    const float cz = g_new[(b*NPNT + s)*3 + 2];
    const float ns = cx*cx + cy*cy + cz*cz;
    const float R2 = 0.01f;

    const float* px = xyz + (size_t)b*3*NPTS;
    int cnt = 0, first = 0;
    int* grp = g_grp + (b*NPNT + s)*NSAMP;

    for (int bs = 0; bs < NPTS; bs += 32) {
        const int n = bs + lane;
        const float xx = px[n], xy = px[NPTS + n], xz = px[2*NPTS + n];
        const float dot = cx*xx + cy*xy + cz*xz;
        const float nx  = xx*xx + xy*xy + xz*xz;
        const float d   = -2.0f*dot + ns + nx;
        const bool ok = !(d > R2);
        const unsigned m = __ballot_sync(0xffffffffu, ok);
        if (m) {
            if (cnt == 0) first = bs + __ffs(m) - 1;
            const int pos = cnt + __popc(m & ((1u << lane) - 1u));
            if (ok && pos < NSAMP) grp[pos] = n;
            cnt += __popc(m);
            if (cnt >= NSAMP) break;
        }
    }
    cnt = min(cnt, NSAMP);
    for (int k = cnt + lane; k < NSAMP; k += 32) grp[k] = first;
}

// ---------------- per-point layer0 partial (UNCHANGED) ----------------
__global__ void __launch_bounds__(256)
a0_kernel(const float* __restrict__ xyz, const float* __restrict__ pts,
          const float* __restrict__ W0, const float* __restrict__ b0)
{
    __shared__ float sWt[CIN0*64];      // [j][co]
    __shared__ float sB[64];
    const int b = blockIdx.y;
    const int n = blockIdx.x*256 + threadIdx.x;
    for (int i = threadIdx.x; i < 64*CIN0; i += 256) {
        const int co = i / CIN0, j = i - co*CIN0;
        sWt[j*64 + co] = W0[i];
    }
    for (int i = threadIdx.x; i < 64; i += 256) sB[i] = b0[i];
    __syncthreads();

    float f[CIN0];
    const float* xb = xyz + (size_t)b*3*NPTS;
    f[0] = xb[n]; f[1] = xb[NPTS + n]; f[2] = xb[2*NPTS + n];
    const float* pb = pts + (size_t)b*64*NPTS;
    #pragma unroll
    for (int j = 0; j < 64; j++) f[3 + j] = pb[(size_t)j*NPTS + n];

    float* outp = g_A0 + ((size_t)b*NPTS + n)*64;
    #pragma unroll 1
    for (int c8 = 0; c8 < 64; c8 += 8) {
        u64 acc[4];
        #pragma unroll
        for (int r = 0; r < 4; r++) acc[r] = pk2(sB[c8 + 2*r], sB[c8 + 2*r + 1]);
        #pragma unroll
        for (int j = 0; j < CIN0; j++) {
            const u64 fd = pk2(f[j], f[j]);
            const ulonglong2 wa = *reinterpret_cast<const ulonglong2*>(sWt + j*64 + c8);
            const ulonglong2 wb = *reinterpret_cast<const ulonglong2*>(sWt + j*64 + c8 + 4);
            ffma2(acc[0], wa.x, fd);
            ffma2(acc[1], wa.y, fd);
            ffma2(acc[2], wb.x, fd);
            ffma2(acc[3], wb.y, fd);
        }
        float v0,v1,v2,v3,v4,v5,v6,v7;
        upk2(acc[0], v0, v1); upk2(acc[1], v2, v3);
        upk2(acc[2], v4, v5); upk2(acc[3], v6, v7);
        *reinterpret_cast<float4*>(outp + c8)     = make_float4(v0, v1, v2, v3);
        *reinterpret_cast<float4*>(outp + c8 + 4) = make_float4(v4, v5, v6, v7);
    }
}

// ---------------- per-centroid layer0 partial (UNCHANGED) ----------------
__global__ void __launch_bounds__(256)
c0_kernel(const float* __restrict__ W0)
{
    __shared__ float sw[192];
    const int b = blockIdx.y;
    const int s = blockIdx.x*256 + threadIdx.x;
    for (int i = threadIdx.x; i < 192; i += 256) sw[i] = W0[(i/3)*CIN0 + (i%3)];
    __syncthreads();

    const float x = g_new[(b*NPNT + s)*3 + 0];
    const float y = g_new[(b*NPNT + s)*3 + 1];
    const float z = g_new[(b*NPNT + s)*3 + 2];
    float* outp = g_C0 + ((size_t)b*NPNT + s)*64;
    #pragma unroll 1
    for (int c4 = 0; c4 < 64; c4 += 4) {
        float4 o;
        o.x = sw[(c4+0)*3]*x + sw[(c4+0)*3+1]*y + sw[(c4+0)*3+2]*z;
        o.y = sw[(c4+1)*3]*x + sw[(c4+1)*3+1]*y + sw[(c4+1)*3+2]*z;
        o.z = sw[(c4+2)*3]*x + sw[(c4+2)*3+1]*y + sw[(c4+2)*3+2]*z;
        o.w = sw[(c4+3)*3]*x + sw[(c4+3)*3+1]*y + sw[(c4+3)*3+2]*z;
        *reinterpret_cast<float4*>(outp + c4) = o;
    }
}

// ---------------- k0s: gather x0 = A0[idx]-C0[s], write + fused BN0 stats ----------------
__global__ void __launch_bounds__(256)
k0s_kernel()
{
    extern __shared__ float smk[];
    float* tile = smk;                            // [64][260]  (66,560 B)
    int*   sidx = (int*)(smk + 64*260);           // 256 idx
    __shared__ float ps[256], pq[256];

    const int b  = blockIdx.y;
    const int p0 = blockIdx.x * 256;              // 256 pixels, same k
    const int k  = p0 >> 10, s0 = p0 & 1023;
    const int tid = threadIdx.x;

    sidx[tid] = g_grp[(b*NPNT + s0 + tid)*NSAMP + k];
    __syncthreads();

    {
        const int idx = sidx[tid];
        const float4* A = (const float4*)(g_A0 + ((size_t)b*NPTS + idx    )*64);
        const float4* C = (const float4*)(g_C0 + ((size_t)b*NPNT + s0+tid )*64);
        #pragma unroll
        for (int u = 0; u < 16; u++) {
            const float4 a  = A[u];
            const float4 c4 = C[u];
            const int c = u*4;
            tile[(c+0)*260 + tid] = a.x - c4.x;
            tile[(c+1)*260 + tid] = a.y - c4.y;
            tile[(c+2)*260 + tid] = a.z - c4.z;
            tile[(c+3)*260 + tid] = a.w - c4.w;
        }
    }
    __syncthreads();

    {
        float* outb = g_x0 + (size_t)b*64*PIX + p0 + tid;
        #pragma unroll 8
        for (int c = 0; c < 64; c++) outb[(size_t)c*PIX] = tile[c*260 + tid];
    }

    {
        const int c = tid & 63, g = tid >> 6;
        const float* row = tile + c*260 + g*64;
        float s = 0.f, q = 0.f;
        #pragma unroll 16
        for (int j = 0; j < 64; j++) { const float v = row[j]; s += v; q = fmaf(v, v, q); }
        ps[tid] = s; pq[tid] = q;
    }
    __syncthreads();
    if (tid < 64) {
        const float S = ((ps[tid] + ps[tid+64]) + ps[tid+128]) + ps[tid+192];
        const float Q = ((pq[tid] + pq[tid+64]) + pq[tid+128]) + pq[tid+192];
        atomicAdd(&g_sumP[0][tid][0], (double)S);
        atomicAdd(&g_sqsP[0][tid][0], (double)Q);
    }
}

// ---------------- fold BN ----------------
__global__ void finalize_kernel(int layer, int C,
                                const float* __restrict__ gamma,
                                const float* __restrict__ beta)
{
    const int c = threadIdx.x;
    if (c >= C) return;
    const double n = (double)BATCH * PIX;
    const double mean = g_sumP[layer][c][0] / n;
    double var = g_sqsP[layer][c][0] / n - mean*mean;
    if (var < 0.0) var = 0.0;
    const float inv = (float)(1.0 / sqrt(var + 1e-5));
    const float a = gamma[c] * inv;
    g_bna[layer][c] = a;
    g_bnc[layer][c] = beta[c] - (float)mean * a;
}

// ---------------- gemm1 (UNCHANGED from r12) ----------------
__global__ void __launch_bounds__(256)
gemm1_kernel(const float* __restrict__ W, const float* __restrict__ bias)
{
    extern __shared__ float smem[];
    float* Xs = smem;                   // 64 x 128
    float* Wd = Xs + 64*128;            // 64 x 128 (dup pairs per co)
    float* sa = Wd + 64*128;
    float* sc = sa + 64;
    float* sb = sc + 64;

    const int b = blockIdx.y;
    const int pbase = blockIdx.x * 128;
    const int tid = threadIdx.x;

    for (int i = tid; i < 64; i += 256) { sa[i] = g_bna[0][i]; sc[i] = g_bnc[0][i]; sb[i] = bias[i]; }
    for (int i = tid; i < 64*64; i += 256) {
        const int co = i >> 6, ci = i & 63;
        const float v = W[i];
        Wd[ci*128 + 2*co]     = v;
        Wd[ci*128 + 2*co + 1] = v;
    }
    __syncthreads();

    const float* xb = g_x0 + (size_t)b*64*PIX + pbase;
    for (int i = tid; i < 64*128; i += 256) {
        const int ci = i >> 7, pp = i & 127;
        Xs[i] = fmaxf(fmaf(xb[(size_t)ci*PIX + pp], sa[ci], sc[ci]), 0.0f);
    }
    __syncthreads();

    const int p0 = (tid & 31) << 2;
    const int c0 = (tid >> 5) << 3;
    u64 acc[8][2];
    #pragma unroll
    for (int r = 0; r < 8; r++) { acc[r][0] = 0ull; acc[r][1] = 0ull; }

    #pragma unroll 8
    for (int ci = 0; ci < 64; ci++) {
        const ulonglong2 xv = *reinterpret_cast<const ulonglong2*>(Xs + (ci << 7) + p0);
        const ulonglong2* wp = reinterpret_cast<const ulonglong2*>(Wd + (ci << 7) + (c0 << 1));
        const ulonglong2 w0 = wp[0], w1 = wp[1], w2 = wp[2], w3 = wp[3];
        ffma2(acc[0][0], w0.x, xv.x); ffma2(acc[0][1], w0.x, xv.y);
        ffma2(acc[1][0], w0.y, xv.x); ffma2(acc[1][1], w0.y, xv.y);
        ffma2(acc[2][0], w1.x, xv.x); ffma2(acc[2][1], w1.x, xv.y);
        ffma2(acc[3][0], w1.y, xv.x); ffma2(acc[3][1], w1.y, xv.y);
        ffma2(acc[4][0], w2.x, xv.x); ffma2(acc[4][1], w2.x, xv.y);
        ffma2(acc[5][0], w2.y, xv.x); ffma2(acc[5][1], w2.y, xv.y);
        ffma2(acc[6][0], w3.x, xv.x); ffma2(acc[6][1], w3.x, xv.y);
        ffma2(acc[7][0], w3.y, xv.x); ffma2(acc[7][1], w3.y, xv.y);
    }

    float ss[8], qq[8];
    #pragma unroll
    for (int r = 0; r < 8; r++) {
        float v0, v1, v2, v3;
        upk2(acc[r][0], v0, v1);
        upk2(acc[r][1], v2, v3);
        const float bb = sb[c0 + r];
        v0 += bb; v1 += bb; v2 += bb; v3 += bb;
        *reinterpret_cast<float4*>(g_x1 + ((size_t)(b*64 + c0 + r))*PIX + pbase + p0)
            = make_float4(v0, v1, v2, v3);
        ss[r] = ((v0 + v1) + v2) + v3;
        qq[r] = fmaf(v3, v3, fmaf(v2, v2, fmaf(v1, v1, v0*v0)));
    }
    const unsigned FULL = 0xffffffffu;
    #pragma unroll
    for (int r = 0; r < 8; r++) {
        #pragma unroll
        for (int o = 16; o; o >>= 1) {
            ss[r] += __shfl_xor_sync(FULL, ss[r], o);
            qq[r] += __shfl_xor_sync(FULL, qq[r], o);
        }
    }
    if ((tid & 31) == 0) {
        #pragma unroll
        for (int r = 0; r < 8; r++) {
            atomicAdd(&g_sumP[1][c0 + r][0], (double)ss[r]);
            atomicAdd(&g_sqsP[1][c0 + r][0], (double)qq[r]);
        }
    }
}

// ---------------- gemm2 (UNCHANGED from r12) ----------------
__global__ void __launch_bounds__(512)
gemm2_kernel(const float* __restrict__ bias)
{
    extern __shared__ float smem[];
    float* Xs = smem;                   // 64 x 64
    float* Wd = Xs + 64*64;             // 64 x 256 (dup pairs per co)
    float* sa = Wd + 64*256;
    float* sc = sa + 64;
    float* sb = sc + 64;                // 128

    const int b  = blockIdx.y;
    const int s0 = blockIdx.x * 64;
    const int tid = threadIdx.x;

    for (int i = tid; i < 64;  i += 512) { sa[i] = g_bna[1][i]; sc[i] = g_bnc[1][i]; }
    for (int i = tid; i < 128; i += 512) sb[i] = bias[i];
    {
        const float4* src = (const float4*)g_W2d;
        float4* dst = (float4*)Wd;
        for (int i = tid; i < 64*256/4; i += 512) dst[i] = src[i];
    }

    const int pcol = (tid & 15) << 2;   // 4 pixels
    const int c0   = (tid >> 4) << 2;   // 4 channels
    float rmax[4][4];
    float ss[4], qq[4];
    #pragma unroll
    for (int r = 0; r < 4; r++) {
        ss[r] = 0.f; qq[r] = 0.f;
        rmax[r][0] = -3.4e38f; rmax[r][1] = -3.4e38f; rmax[r][2] = -3.4e38f; rmax[r][3] = -3.4e38f;
    }

    const float* xb = g_x1 + (size_t)b*64*PIX + s0;
    float st[8];
    #pragma unroll
    for (int j = 0; j < 8; j++) {
        const int i = tid + j*512;
        st[j] = xb[(size_t)(i >> 6)*PIX + (i & 63)];
    }

    for (int k = 0; k < NSAMP; k++) {
        __syncthreads();
        #pragma unroll
        for (int j = 0; j < 8; j++) {
            const int i = tid + j*512;
            const int ci = i >> 6;
            Xs[i] = fmaxf(fmaf(st[j], sa[ci], sc[ci]), 0.0f);
        }
        __syncthreads();
        if (k + 1 < NSAMP) {
            const float* xk = xb + (k+1)*NPNT;
            #pragma unroll
            for (int j = 0; j < 8; j++) {
                const int i = tid + j*512;
                st[j] = xk[(size_t)(i >> 6)*PIX + (i & 63)];
            }
        }

        u64 acc[4][2];
        #pragma unroll
        for (int r = 0; r < 4; r++) { acc[r][0] = 0ull; acc[r][1] = 0ull; }

        #pragma unroll 8
        for (int ci = 0; ci < 64; ci++) {
            const ulonglong2 xv = *reinterpret_cast<const ulonglong2*>(Xs + (ci << 6) + pcol);
            const ulonglong2* wp = reinterpret_cast<const ulonglong2*>(Wd + (ci << 8) + (c0 << 1));
            const ulonglong2 w0 = wp[0], w1 = wp[1];
            ffma2(acc[0][0], w0.x, xv.x); ffma2(acc[0][1], w0.x, xv.y);
            ffma2(acc[1][0], w0.y, xv.x); ffma2(acc[1][1], w0.y, xv.y);
            ffma2(acc[2][0], w1.x, xv.x); ffma2(acc[2][1], w1.x, xv.y);
            ffma2(acc[3][0], w1.y, xv.x); ffma2(acc[3][1], w1.y, xv.y);
        }

        #pragma unroll
        for (int r = 0; r < 4; r++) {
            float v0, v1, v2, v3;
            upk2(acc[r][0], v0, v1);
            upk2(acc[r][1], v2, v3);
            const float bb = sb[c0 + r];
            v0 += bb; v1 += bb; v2 += bb; v3 += bb;
            rmax[r][0] = fmaxf(rmax[r][0], v0);
            rmax[r][1] = fmaxf(rmax[r][1], v1);
            rmax[r][2] = fmaxf(rmax[r][2], v2);
            rmax[r][3] = fmaxf(rmax[r][3], v3);
            ss[r] += v0; qq[r] = fmaf(v0, v0, qq[r]);
            ss[r] += v1; qq[r] = fmaf(v1, v1, qq[r]);
            ss[r] += v2; qq[r] = fmaf(v2, v2, qq[r]);
            ss[r] += v3; qq[r] = fmaf(v3, v3, qq[r]);
        }
    }

    #pragma unroll
    for (int r = 0; r < 4; r++) {
        *reinterpret_cast<float4*>(g_max + (((size_t)(b*128 + c0 + r)) << 10) + s0 + pcol)
            = make_float4(rmax[r][0], rmax[r][1], rmax[r][2], rmax[r][3]);
    }
    const unsigned FULL = 0xffffffffu;
    #pragma unroll
    for (int r = 0; r < 4; r++) {
        #pragma unroll
        for (int o = 8; o; o >>= 1) {
            ss[r] += __shfl_xor_sync(FULL, ss[r], o);
            qq[r] += __shfl_xor_sync(FULL, qq[r], o);
        }
    }
    if ((tid & 15) == 0) {
        #pragma unroll
        for (int r = 0; r < 4; r++) {
            atomicAdd(&g_sumP[2][c0 + r][0], (double)ss[r]);
            atomicAdd(&g_sqsP[2][c0 + r][0], (double)qq[r]);
        }
    }
}

// ---------------- apply BN2+relu to the raw max ----------------
__global__ void __launch_bounds__(256)
maxapply_kernel(float* __restrict__ out)
{
    const int idx = blockIdx.x*256 + threadIdx.x;
    const int co  = (idx >> 10) & 127;
    const float v = g_max[idx];
    out[BATCH*3*NPNT + idx] = fmaxf(fmaf(v, g_bna[2][co], g_bnc[2][co]), 0.0f);
}

// ---------------- launcher ----------------
extern "C" void kernel_launch(void* const* d_in, const int* in_sizes, int n_in,
                              void* d_out, int out_size)
{
    const float* xyz = (const float*)d_in[0];
    const float* pts = (const float*)d_in[1];
    const float* W0  = (const float*)d_in[2];
    const float* b0  = (const float*)d_in[3];
    const float* ga0 = (const float*)d_in[4];
    const float* be0 = (const float*)d_in[5];
    const float* W1  = (const float*)d_in[6];
    const float* b1  = (const float*)d_in[7];
    const float* ga1 = (const float*)d_in[8];
    const float* be1 = (const float*)d_in[9];
    const float* W2  = (const float*)d_in[10];
    const float* b2  = (const float*)d_in[11];
    const float* ga2 = (const float*)d_in[12];
    const float* be2 = (const float*)d_in[13];
    float* out = (float*)d_out;

    const int FPS_SMEM = (3*NPTS)*4 + NPNT*4;              // 53,248
    const int K0_SMEM  = (64*260)*4 + 256*4;               // 67,584
    const int SM1 = (64*128 + 64*128 + 64+64+64 ) * 4;     // 66,304
    const int SM2 = (64*64  + 64*256 + 64+64+128) * 4;     // 82,944
    cudaFuncSetAttribute((const void*)fps_kernel,   cudaFuncAttributeMaxDynamicSharedMemorySize, FPS_SMEM);
    cudaFuncSetAttribute((const void*)k0s_kernel,   cudaFuncAttributeMaxDynamicSharedMemorySize, K0_SMEM);
    cudaFuncSetAttribute((const void*)gemm1_kernel, cudaFuncAttributeMaxDynamicSharedMemorySize, SM1);
    cudaFuncSetAttribute((const void*)gemm2_kernel, cudaFuncAttributeMaxDynamicSharedMemorySize, SM2);

    // order keeps fps in the profiler's 4th-launch capture slot
    zero_stats_kernel<<<1, 384>>>();
    a0_kernel  <<<dim3(NPTS/256, BATCH), 256>>>(xyz, pts, W0, b0);
    dupw2_kernel<<<32, 256>>>(W2);
    fps_kernel <<<BATCH, 256, FPS_SMEM>>>(xyz, out);
    ball_kernel<<<(BATCH*NPNT*32)/256, 256>>>(xyz);
    c0_kernel  <<<dim3(NPNT/256, BATCH), 256>>>(W0);
    k0s_kernel <<<dim3(PIX/256, BATCH), 256, K0_SMEM>>>();

    finalize_kernel<<<1, 128>>>(0, 64, ga0, be0);
    gemm1_kernel   <<<dim3(PIX/128, BATCH), 256, SM1>>>(W1, b1);

    finalize_kernel<<<1, 128>>>(1, 64, ga1, be1);
    gemm2_kernel   <<<dim3(NPNT/64, BATCH), 512, SM2>>>(b2);

    finalize_kernel<<<1, 128>>>(2, 128, ga2, be2);
    maxapply_kernel<<<(BATCH*128*NPNT)/256, 256>>>(out);
}

// round 15
// speedup vs baseline: 1.7170x; 1.0467x over previous
#include <cuda_runtime.h>
#include <math.h>

#define BATCH   16
#define NPTS    4096
#define NPNT    1024
#define NSAMP   32
#define PIX     (NSAMP*NPNT)      // 32768 pixels per batch
#define CIN0    67

typedef unsigned long long u64;
__device__ __forceinline__ u64 pk2(float lo, float hi) {
    u64 r; asm("mov.b64 %0,{%1,%2};" : "=l"(r) : "f"(lo), "f"(hi)); return r;
}
__device__ __forceinline__ void upk2(u64 v, float& lo, float& hi) {
    asm("mov.b64 {%0,%1},%2;" : "=f"(lo), "=f"(hi) : "l"(v));
}
__device__ __forceinline__ void ffma2(u64& d, u64 a, u64 b) {
    asm("fma.rn.f32x2 %0,%1,%2,%0;" : "+l"(d) : "l"(a), "l"(b));
}
__device__ __forceinline__ u64 add2(u64 a, u64 b) {
    u64 r; asm("add.rn.f32x2 %0,%1,%2;" : "=l"(r) : "l"(a), "l"(b)); return r;
}
__device__ __forceinline__ u64 mul2(u64 a, u64 b) {
    u64 r; asm("mul.rn.f32x2 %0,%1,%2;" : "=l"(r) : "l"(a), "l"(b)); return r;
}

// ---------------- device scratch (static: no allocs allowed) ----------------
__device__ int    g_grp[BATCH*NPNT*NSAMP];
__device__ float  g_new[BATCH*NPNT*3];
__device__ float  g_A0 [BATCH*NPTS*64];
__device__ float  g_C0 [BATCH*NPNT*64];
__device__ float  g_x0 [(size_t)BATCH*64 *PIX];
__device__ float  g_x1 [(size_t)BATCH*64 *PIX];
__device__ float  g_max[(size_t)BATCH*128*NPNT];
__device__ float  g_W2d[64*256];                 // W2 pre-duplicated [ci][2*co{dup}]
// 256B-strided accumulators: channels spread across L2 slices
__device__ double g_sumP[3][128][32];
__device__ double g_sqsP[3][128][32];
__device__ float  g_bna[3][128];
__device__ float  g_bnc[3][128];

__global__ void zero_stats_kernel() {
    int i = threadIdx.x;
    if (i < 384) {
        const int l = i >> 7, c = i & 127;
        g_sumP[l][c][0] = 0.0;
        g_sqsP[l][c][0] = 0.0;
    }
}

// ---------------- W2 duplication (profiler slot filler) ----------------
__global__ void __launch_bounds__(256)
dupw2_kernel(const float* __restrict__ W)
{
    const int i = blockIdx.x*256 + threadIdx.x;    // 8192 = 128*64
    const int co = i >> 6, ci = i & 63;
    const float v = W[i];
    g_W2d[ci*256 + 2*co]     = v;
    g_W2d[ci*256 + 2*co + 1] = v;
}

// ---------------- FPS: EXACT r11/r14 kernel (measured 273.9us) ----------------
__global__ void __launch_bounds__(256, 1)
fps_kernel(const float* __restrict__ xyz, float* __restrict__ out)
{
    extern __shared__ float sm[];
    float* sx = sm;                              // 4096
    float* sy = sm + NPTS;
    float* sz = sm + 2*NPTS;
    int*   sfi = (int*)(sm + 3*NPTS);            // 1024 selected indices
    __shared__ u64 part[2][8];

    const int b = blockIdx.x, t = threadIdx.x;
    const int lane = t & 31, wid = t >> 5;
    const unsigned FULL = 0xffffffffu;
    const float* base = xyz + (size_t)b*3*NPTS;
    for (int n = t; n < NPTS; n += 256) {
        sx[n] = base[n];
        sy[n] = base[NPTS + n];
        sz[n] = base[2*NPTS + n];
    }
    __syncthreads();

    u64 xp[8], yp[8], zp[8];
    #pragma unroll
    for (int j = 0; j < 8; j++) {
        const int p = t + j*256;
        xp[j] = pk2(sx[2*p], sx[2*p+1]);
        yp[j] = pk2(sy[2*p], sy[2*p+1]);
        zp[j] = pk2(sz[2*p], sz[2*p+1]);
    }
    float d[16];
    #pragma unroll
    for (int r = 0; r < 16; r++) d[r] = 1e10f;

    int far = 0;
    for (int i = 0; i < NPNT; i++) {
        const float cx = sx[far], cy = sy[far], cz = sz[far];
        const u64 ncx = pk2(-cx, -cx), ncy = pk2(-cy, -cy), ncz = pk2(-cz, -cz);
        if (t == 0) sfi[i] = far;

        float bv = -1.0f; int bi = 0;
        #pragma unroll
        for (int j = 0; j < 8; j++) {
            const u64 dx = add2(xp[j], ncx);
            const u64 dy = add2(yp[j], ncy);
            const u64 dz = add2(zp[j], ncz);
            const u64 dd = add2(add2(mul2(dx, dx), mul2(dy, dy)), mul2(dz, dz));
            float f0, f1; upk2(dd, f0, f1);
            const int n0 = 2*(t + j*256);
            float& a0 = d[2*j];
            float& a1 = d[2*j + 1];
            a0 = fminf(a0, f0); if (a0 > bv) { bv = a0; bi = n0; }
            a1 = fminf(a1, f1); if (a1 > bv) { bv = a1; bi = n0 + 1; }
        }
        const unsigned bits = __float_as_uint(bv);
        const unsigned mx   = __reduce_max_sync(FULL, bits);
        const int cand      = (bits == mx) ? bi : 0x7fffffff;
        const int wmin      = __reduce_min_sync(FULL, cand);
        if (lane == 0) part[i & 1][wid] = ((u64)mx << 32) | (unsigned)wmin;
        __syncthreads();
        const u64 v = part[i & 1][lane & 7];
        const unsigned pb = (unsigned)(v >> 32);
        const unsigned m2 = __reduce_max_sync(FULL, pb);
        const int c2 = (pb == m2) ? (int)(unsigned)(v & 0xffffffffu) : 0x7fffffff;
        far = __reduce_min_sync(FULL, c2);
    }
    __syncthreads();
    for (int i = t; i < NPNT; i += 256) {
        const int f = sfi[i];
        const float cx = sx[f], cy = sy[f], cz = sz[f];
        g_new[(b*NPNT + i)*3 + 0] = cx;
        g_new[(b*NPNT + i)*3 + 1] = cy;
        g_new[(b*NPNT + i)*3 + 2] = cz;
        out[b*3*NPNT            + i] = cx;
        out[b*3*NPNT +   NPNT   + i] = cy;
        out[b*3*NPNT + 2*NPNT   + i] = cz;
    }
}

// ---------------- ball query (UNCHANGED — passing arithmetic) ----------------
__global__ void __launch_bounds__(256)
ball_kernel(const float* __restrict__ xyz)
{
    const int w    = (blockIdx.x*blockDim.x + threadIdx.x) >> 5;
    const int lane = threadIdx.x & 31;
    const int b = w / NPNT, s = w % NPNT;

    const float cx = g_new[(b*NPNT + s)*3 + 0];
    const float cy = g_new[(b*NPNT + s)*3 + 1];
    const float cz = g_new[(b*NPNT + s)*3 + 2];
    const float ns = cx*cx + cy*cy + cz*cz;
    const float R2 = 0.01f;

    const float* px = xyz + (size_t)b*3*NPTS;
    int cnt = 0, first = 0;
    int* grp = g_grp + (b*NPNT + s)*NSAMP;

    for (int bs = 0; bs < NPTS; bs += 32) {
        const int n = bs + lane;
        const float xx = px[n], xy = px[NPTS + n], xz = px[2*NPTS + n];
        const float dot = cx*xx + cy*xy + cz*xz;
        const float nx  = xx*xx + xy*xy + xz*xz;
        const float d   = -2.0f*dot + ns + nx;
        const bool ok = !(d > R2);
        const unsigned m = __ballot_sync(0xffffffffu, ok);
        if (m) {
            if (cnt == 0) first = bs + __ffs(m) - 1;
            const int pos = cnt + __popc(m & ((1u << lane) - 1u));
            if (ok && pos < NSAMP) grp[pos] = n;
            cnt += __popc(m);
            if (cnt >= NSAMP) break;
        }
    }
    cnt = min(cnt, NSAMP);
    for (int k = cnt + lane; k < NSAMP; k += 32) grp[k] = first;
}

// ---------------- per-point layer0 partial (UNCHANGED) ----------------
__global__ void __launch_bounds__(256)
a0_kernel(const float* __restrict__ xyz, const float* __restrict__ pts,
          const float* __restrict__ W0, const float* __restrict__ b0)
{
    __shared__ float sWt[CIN0*64];      // [j][co]
    __shared__ float sB[64];
    const int b = blockIdx.y;
    const int n = blockIdx.x*256 + threadIdx.x;
    for (int i = threadIdx.x; i < 64*CIN0; i += 256) {
        const int co = i / CIN0, j = i - co*CIN0;
        sWt[j*64 + co] = W0[i];
    }
    for (int i = threadIdx.x; i < 64; i += 256) sB[i] = b0[i];
    __syncthreads();

    float f[CIN0];
    const float* xb = xyz + (size_t)b*3*NPTS;
    f[0] = xb[n]; f[1] = xb[NPTS + n]; f[2] = xb[2*NPTS + n];
    const float* pb = pts + (size_t)b*64*NPTS;
    #pragma unroll
    for (int j = 0; j < 64; j++) f[3 + j] = pb[(size_t)j*NPTS + n];

    float* outp = g_A0 + ((size_t)b*NPTS + n)*64;
    #pragma unroll 1
    for (int c8 = 0; c8 < 64; c8 += 8) {
        u64 acc[4];
        #pragma unroll
        for (int r = 0; r < 4; r++) acc[r] = pk2(sB[c8 + 2*r], sB[c8 + 2*r + 1]);
        #pragma unroll
        for (int j = 0; j < CIN0; j++) {
            const u64 fd = pk2(f[j], f[j]);
            const ulonglong2 wa = *reinterpret_cast<const ulonglong2*>(sWt + j*64 + c8);
            const ulonglong2 wb = *reinterpret_cast<const ulonglong2*>(sWt + j*64 + c8 + 4);
            ffma2(acc[0], wa.x, fd);
            ffma2(acc[1], wa.y, fd);
            ffma2(acc[2], wb.x, fd);
            ffma2(acc[3], wb.y, fd);
        }
        float v0,v1,v2,v3,v4,v5,v6,v7;
        upk2(acc[0], v0, v1); upk2(acc[1], v2, v3);
        upk2(acc[2], v4, v5); upk2(acc[3], v6, v7);
        *reinterpret_cast<float4*>(outp + c8)     = make_float4(v0, v1, v2, v3);
        *reinterpret_cast<float4*>(outp + c8 + 4) = make_float4(v4, v5, v6, v7);
    }
}

// ---------------- per-centroid layer0 partial (UNCHANGED) ----------------
__global__ void __launch_bounds__(256)
c0_kernel(const float* __restrict__ W0)
{
    __shared__ float sw[192];
    const int b = blockIdx.y;
    const int s = blockIdx.x*256 + threadIdx.x;
    for (int i = threadIdx.x; i < 192; i += 256) sw[i] = W0[(i/3)*CIN0 + (i%3)];
    __syncthreads();

    const float x = g_new[(b*NPNT + s)*3 + 0];
    const float y = g_new[(b*NPNT + s)*3 + 1];
    const float z = g_new[(b*NPNT + s)*3 + 2];
    float* outp = g_C0 + ((size_t)b*NPNT + s)*64;
    #pragma unroll 1
    for (int c4 = 0; c4 < 64; c4 += 4) {
        float4 o;
        o.x = sw[(c4+0)*3]*x + sw[(c4+0)*3+1]*y + sw[(c4+0)*3+2]*z;
        o.y = sw[(c4+1)*3]*x + sw[(c4+1)*3+1]*y + sw[(c4+1)*3+2]*z;
        o.z = sw[(c4+2)*3]*x + sw[(c4+2)*3+1]*y + sw[(c4+2)*3+2]*z;
        o.w = sw[(c4+3)*3]*x + sw[(c4+3)*3+1]*y + sw[(c4+3)*3+2]*z;
        *reinterpret_cast<float4*>(outp + c4) = o;
    }
}

// ---------------- k0s: gather x0 = A0[idx]-C0[s], write + fused BN0 stats ----------------
__global__ void __launch_bounds__(256)
k0s_kernel()
{
    extern __shared__ float smk[];
    float* tile = smk;                            // [64][260]
    int*   sidx = (int*)(smk + 64*260);           // 256 idx
    __shared__ float ps[256], pq[256];

    const int b  = blockIdx.y;
    const int p0 = blockIdx.x * 256;              // 256 pixels, same k
    const int k  = p0 >> 10, s0 = p0 & 1023;
    const int tid = threadIdx.x;

    sidx[tid] = g_grp[(b*NPNT + s0 + tid)*NSAMP + k];
    __syncthreads();

    {
        const int idx = sidx[tid];
        const float4* A = (const float4*)(g_A0 + ((size_t)b*NPTS + idx    )*64);
        const float4* C = (const float4*)(g_C0 + ((size_t)b*NPNT + s0+tid )*64);
        #pragma unroll
        for (int u = 0; u < 16; u++) {
            const float4 a  = A[u];
            const float4 c4 = C[u];
            const int c = u*4;
            tile[(c+0)*260 + tid] = a.x - c4.x;
            tile[(c+1)*260 + tid] = a.y - c4.y;
            tile[(c+2)*260 + tid] = a.z - c4.z;
            tile[(c+3)*260 + tid] = a.w - c4.w;
        }
    }
    __syncthreads();

    {
        float* outb = g_x0 + (size_t)b*64*PIX + p0 + tid;
        #pragma unroll 8
        for (int c = 0; c < 64; c++) outb[(size_t)c*PIX] = tile[c*260 + tid];
    }

    {
        const int c = tid & 63, g = tid >> 6;
        const float* row = tile + c*260 + g*64;
        float s = 0.f, q = 0.f;
        #pragma unroll 16
        for (int j = 0; j < 64; j++) { const float v = row[j]; s += v; q = fmaf(v, v, q); }
        ps[tid] = s; pq[tid] = q;
    }
    __syncthreads();
    if (tid < 64) {
        const float S = ((ps[tid] + ps[tid+64]) + ps[tid+128]) + ps[tid+192];
        const float Q = ((pq[tid] + pq[tid+64]) + pq[tid+128]) + pq[tid+192];
        atomicAdd(&g_sumP[0][tid][0], (double)S);
        atomicAdd(&g_sqsP[0][tid][0], (double)Q);
    }
}

// ---------------- fold BN ----------------
__global__ void finalize_kernel(int layer, int C,
                                const float* __restrict__ gamma,
                                const float* __restrict__ beta)
{
    const int c = threadIdx.x;
    if (c >= C) return;
    const double n = (double)BATCH * PIX;
    const double mean = g_sumP[layer][c][0] / n;
    double var = g_sqsP[layer][c][0] / n - mean*mean;
    if (var < 0.0) var = 0.0;
    const float inv = (float)(1.0 / sqrt(var + 1e-5));
    const float a = gamma[c] * inv;
    g_bna[layer][c] = a;
    g_bnc[layer][c] = beta[c] - (float)mean * a;
}

// ---------------- gemm1: 256-px tiles, 8px x 8co per thread ----------------
__global__ void __launch_bounds__(256)
gemm1_kernel(const float* __restrict__ W, const float* __restrict__ bias)
{
    extern __shared__ float smem[];
    float* Xs = smem;                   // 64 x 256  (64KB)
    float* Wd = Xs + 64*256;            // 64 x 128 (dup pairs per co, 32KB)
    float* sa = Wd + 64*128;
    float* sc = sa + 64;
    float* sb = sc + 64;

    const int b = blockIdx.y;
    const int pbase = blockIdx.x * 256;
    const int tid = threadIdx.x;

    for (int i = tid; i < 64; i += 256) { sa[i] = g_bna[0][i]; sc[i] = g_bnc[0][i]; sb[i] = bias[i]; }
    for (int i = tid; i < 64*64; i += 256) {
        const int co = i >> 6, ci = i & 63;
        const float v = W[i];
        Wd[ci*128 + 2*co]     = v;
        Wd[ci*128 + 2*co + 1] = v;
    }
    __syncthreads();

    const float* xb = g_x0 + (size_t)b*64*PIX + pbase;
    for (int i = tid; i < 64*256; i += 256) {
        const int ci = i >> 8, pp = i & 255;
        Xs[i] = fmaxf(fmaf(xb[(size_t)ci*PIX + pp], sa[ci], sc[ci]), 0.0f);
    }
    __syncthreads();

    const int p0 = (tid & 31) << 3;     // 8 pixels
    const int c0 = (tid >> 5) << 3;     // 8 channels
    u64 acc[8][4];                      // [co][px-pair]
    #pragma unroll
    for (int r = 0; r < 8; r++) { acc[r][0]=0ull; acc[r][1]=0ull; acc[r][2]=0ull; acc[r][3]=0ull; }

    #pragma unroll 4
    for (int ci = 0; ci < 64; ci++) {
        const ulonglong2 xa = *reinterpret_cast<const ulonglong2*>(Xs + (ci << 8) + p0);
        const ulonglong2 xc = *reinterpret_cast<const ulonglong2*>(Xs + (ci << 8) + p0 + 4);
        const u64 xq[4] = {xa.x, xa.y, xc.x, xc.y};
        const ulonglong2* wp = reinterpret_cast<const ulonglong2*>(Wd + (ci << 7) + (c0 << 1));
        const ulonglong2 w0 = wp[0], w1 = wp[1], w2 = wp[2], w3 = wp[3];
        const u64 wv[8] = {w0.x, w0.y, w1.x, w1.y, w2.x, w2.y, w3.x, w3.y};
        #pragma unroll
        for (int r = 0; r < 8; r++)
            #pragma unroll
            for (int q = 0; q < 4; q++)
                ffma2(acc[r][q], wv[r], xq[q]);
    }

    float ss[8], qq[8];
    #pragma unroll
    for (int r = 0; r < 8; r++) {
        float v0,v1,v2,v3,v4,v5,v6,v7;
        upk2(acc[r][0], v0, v1); upk2(acc[r][1], v2, v3);
        upk2(acc[r][2], v4, v5); upk2(acc[r][3], v6, v7);
        const float bb = sb[c0 + r];
        v0 += bb; v1 += bb; v2 += bb; v3 += bb;
        v4 += bb; v5 += bb; v6 += bb; v7 += bb;
        float* yb = g_x1 + ((size_t)(b*64 + c0 + r))*PIX + pbase + p0;
        *reinterpret_cast<float4*>(yb)     = make_float4(v0, v1, v2, v3);
        *reinterpret_cast<float4*>(yb + 4) = make_float4(v4, v5, v6, v7);
        ss[r] = (((v0 + v1) + v2) + v3) + (((v4 + v5) + v6) + v7);
        qq[r] = fmaf(v7, v7, fmaf(v6, v6, fmaf(v5, v5, fmaf(v4, v4,
                fmaf(v3, v3, fmaf(v2, v2, fmaf(v1, v1, v0*v0)))))));
    }
    const unsigned FULL = 0xffffffffu;
    #pragma unroll
    for (int r = 0; r < 8; r++) {
        #pragma unroll
        for (int o = 16; o; o >>= 1) {
            ss[r] += __shfl_xor_sync(FULL, ss[r], o);
            qq[r] += __shfl_xor_sync(FULL, qq[r], o);
        }
    }
    if ((tid & 31) == 0) {
        #pragma unroll
        for (int r = 0; r < 8; r++) {
            atomicAdd(&g_sumP[1][c0 + r][0], (double)ss[r]);
            atomicAdd(&g_sqsP[1][c0 + r][0], (double)qq[r]);
        }
    }
}

// ---------------- gemm2: 4-k batched X stage (W reads amortized 4x) ----------------
__global__ void __launch_bounds__(512)
gemm2_kernel(const float* __restrict__ bias)
{
    extern __shared__ float smem[];
    float* Xs = smem;                   // 4 x (64 x 64)  (64KB)
    float* Wd = Xs + 4*4096;            // 64 x 256 (dup pairs per co, 64KB)
    float* sa = Wd + 64*256;
    float* sc = sa + 64;
    float* sb = sc + 64;                // 128

    const int b  = blockIdx.y;
    const int s0 = blockIdx.x * 64;
    const int tid = threadIdx.x;

    for (int i = tid; i < 64;  i += 512) { sa[i] = g_bna[1][i]; sc[i] = g_bnc[1][i]; }
    for (int i = tid; i < 128; i += 512) sb[i] = bias[i];
    {
        const float4* src = (const float4*)g_W2d;
        float4* dst = (float4*)Wd;
        for (int i = tid; i < 64*256/4; i += 512) dst[i] = src[i];
    }

    const int pcol = (tid & 15) << 2;   // 4 pixels
    const int c0   = (tid >> 4) << 2;   // 4 channels
    float rmax[4][4];
    float ss[4], qq[4];
    #pragma unroll
    for (int r = 0; r < 4; r++) {
        ss[r] = 0.f; qq[r] = 0.f;
        rmax[r][0] = -3.4e38f; rmax[r][1] = -3.4e38f; rmax[r][2] = -3.4e38f; rmax[r][3] = -3.4e38f;
    }

    const float* xb = g_x1 + (size_t)b*64*PIX + s0;

    for (int ph = 0; ph < NSAMP/4; ph++) {
        __syncthreads();
        #pragma unroll
        for (int kk = 0; kk < 4; kk++) {
            const float* xk = xb + (ph*4 + kk)*NPNT;
            #pragma unroll
            for (int j = 0; j < 8; j++) {
                const int i = tid + j*512;
                const int ci = i >> 6;
                Xs[kk*4096 + i] = fmaxf(fmaf(xk[(size_t)ci*PIX + (i & 63)], sa[ci], sc[ci]), 0.0f);
            }
        }
        __syncthreads();

        u64 acc[4][4][2];               // [k][co][px-pair]
        #pragma unroll
        for (int kk = 0; kk < 4; kk++)
            #pragma unroll
            for (int r = 0; r < 4; r++) { acc[kk][r][0] = 0ull; acc[kk][r][1] = 0ull; }

        #pragma unroll 4
        for (int ci = 0; ci < 64; ci++) {
            const ulonglong2* wp = reinterpret_cast<const ulonglong2*>(Wd + (ci << 8) + (c0 << 1));
            const ulonglong2 w0 = wp[0], w1 = wp[1];
            const u64 wv[4] = {w0.x, w0.y, w1.x, w1.y};
            #pragma unroll
            for (int kk = 0; kk < 4; kk++) {
                const ulonglong2 xv = *reinterpret_cast<const ulonglong2*>(Xs + kk*4096 + (ci << 6) + pcol);
                #pragma unroll
                for (int r = 0; r < 4; r++) {
                    ffma2(acc[kk][r][0], wv[r], xv.x);
                    ffma2(acc[kk][r][1], wv[r], xv.y);
                }
            }
        }

        #pragma unroll
        for (int kk = 0; kk < 4; kk++) {
            #pragma unroll
            for (int r = 0; r < 4; r++) {
                float v0, v1, v2, v3;
                upk2(acc[kk][r][0], v0, v1);
                upk2(acc[kk][r][1], v2, v3);
                const float bb = sb[c0 + r];
                v0 += bb; v1 += bb; v2 += bb; v3 += bb;
                rmax[r][0] = fmaxf(rmax[r][0], v0);
                rmax[r][1] = fmaxf(rmax[r][1], v1);
                rmax[r][2] = fmaxf(rmax[r][2], v2);
                rmax[r][3] = fmaxf(rmax[r][3], v3);
                ss[r] += v0; qq[r] = fmaf(v0, v0, qq[r]);
                ss[r] += v1; qq[r] = fmaf(v1, v1, qq[r]);
                ss[r] += v2; qq[r] = fmaf(v2, v2, qq[r]);
                ss[r] += v3; qq[r] = fmaf(v3, v3, qq[r]);
            }
        }
    }

    #pragma unroll
    for (int r = 0; r < 4; r++) {
        *reinterpret_cast<float4*>(g_max + (((size_t)(b*128 + c0 + r)) << 10) + s0 + pcol)
            = make_float4(rmax[r][0], rmax[r][1], rmax[r][2], rmax[r][3]);
    }
    const unsigned FULL = 0xffffffffu;
    #pragma unroll
    for (int r = 0; r < 4; r++) {
        #pragma unroll
        for (int o = 8; o; o >>= 1) {
            ss[r] += __shfl_xor_sync(FULL, ss[r], o);
            qq[r] += __shfl_xor_sync(FULL, qq[r], o);
        }
    }
    if ((tid & 15) == 0) {
        #pragma unroll
        for (int r = 0; r < 4; r++) {
            atomicAdd(&g_sumP[2][c0 + r][0], (double)ss[r]);
            atomicAdd(&g_sqsP[2][c0 + r][0], (double)qq[r]);
        }
    }
}

// ---------------- apply BN2+relu to the raw max ----------------
__global__ void __launch_bounds__(256)
maxapply_kernel(float* __restrict__ out)
{
    const int idx = blockIdx.x*256 + threadIdx.x;
    const int co  = (idx >> 10) & 127;
    const float v = g_max[idx];
    out[BATCH*3*NPNT + idx] = fmaxf(fmaf(v, g_bna[2][co], g_bnc[2][co]), 0.0f);
}

// ---------------- launcher ----------------
extern "C" void kernel_launch(void* const* d_in, const int* in_sizes, int n_in,
                              void* d_out, int out_size)
{
    const float* xyz = (const float*)d_in[0];
    const float* pts = (const float*)d_in[1];
    const float* W0  = (const float*)d_in[2];
    const float* b0  = (const float*)d_in[3];
    const float* ga0 = (const float*)d_in[4];
    const float* be0 = (const float*)d_in[5];
    const float* W1  = (const float*)d_in[6];
    const float* b1  = (const float*)d_in[7];
    const float* ga1 = (const float*)d_in[8];
    const float* be1 = (const float*)d_in[9];
    const float* W2  = (const float*)d_in[10];
    const float* b2  = (const float*)d_in[11];
    const float* ga2 = (const float*)d_in[12];
    const float* be2 = (const float*)d_in[13];
    float* out = (float*)d_out;

    const int FPS_SMEM = (3*NPTS)*4 + NPNT*4;              // 53,248
    const int K0_SMEM  = (64*260)*4 + 256*4;               // 67,584
    const int SM1 = (64*256 + 64*128 + 64+64+64 ) * 4;     // 99,072
    const int SM2 = (4*4096 + 64*256 + 64+64+128) * 4;     // 132,096
    cudaFuncSetAttribute((const void*)fps_kernel,   cudaFuncAttributeMaxDynamicSharedMemorySize, FPS_SMEM);
    cudaFuncSetAttribute((const void*)k0s_kernel,   cudaFuncAttributeMaxDynamicSharedMemorySize, K0_SMEM);
    cudaFuncSetAttribute((const void*)gemm1_kernel, cudaFuncAttributeMaxDynamicSharedMemorySize, SM1);
    cudaFuncSetAttribute((const void*)gemm2_kernel, cudaFuncAttributeMaxDynamicSharedMemorySize, SM2);

    // order keeps fps in the profiler's 4th-launch capture slot
    zero_stats_kernel<<<1, 384>>>();
    a0_kernel  <<<dim3(NPTS/256, BATCH), 256>>>(xyz, pts, W0, b0);
    dupw2_kernel<<<32, 256>>>(W2);
    fps_kernel <<<BATCH, 256, FPS_SMEM>>>(xyz, out);
    ball_kernel<<<(BATCH*NPNT*32)/256, 256>>>(xyz);
    c0_kernel  <<<dim3(NPNT/256, BATCH), 256>>>(W0);
    k0s_kernel <<<dim3(PIX/256, BATCH), 256, K0_SMEM>>>();

    finalize_kernel<<<1, 128>>>(0, 64, ga0, be0);
    gemm1_kernel   <<<dim3(PIX/256, BATCH), 256, SM1>>>(W1, b1);

    finalize_kernel<<<1, 128>>>(1, 64, ga1, be1);
    gemm2_kernel   <<<dim3(NPNT/64, BATCH), 512, SM2>>>(b2);

    finalize_kernel<<<1, 128>>>(2, 128, ga2, be2);
    maxapply_kernel<<<(BATCH*128*NPNT)/256, 256>>>(out);
}

// round 17
// speedup vs baseline: 1.7882x; 1.0415x over previous
#include <cuda_runtime.h>
#include <math.h>

#define BATCH   16
#define NPTS    4096
#define NPNT    1024
#define NSAMP   32
#define PIX     (NSAMP*NPNT)      // 32768 pixels per batch
#define CIN0    67

typedef unsigned long long u64;
__device__ __forceinline__ u64 pk2(float lo, float hi) {
    u64 r; asm("mov.b64 %0,{%1,%2};" : "=l"(r) : "f"(lo), "f"(hi)); return r;
}
__device__ __forceinline__ void upk2(u64 v, float& lo, float& hi) {
    asm("mov.b64 {%0,%1},%2;" : "=f"(lo), "=f"(hi) : "l"(v));
}
__device__ __forceinline__ void ffma2(u64& d, u64 a, u64 b) {
    asm("fma.rn.f32x2 %0,%1,%2,%0;" : "+l"(d) : "l"(a), "l"(b));
}
__device__ __forceinline__ u64 add2(u64 a, u64 b) {
    u64 r; asm("add.rn.f32x2 %0,%1,%2;" : "=l"(r) : "l"(a), "l"(b)); return r;
}
__device__ __forceinline__ u64 mul2(u64 a, u64 b) {
    u64 r; asm("mul.rn.f32x2 %0,%1,%2;" : "=l"(r) : "l"(a), "l"(b)); return r;
}

// ---------------- device scratch (static: no allocs allowed) ----------------
__device__ int    g_grp[BATCH*NPNT*NSAMP];
__device__ float  g_new[BATCH*NPNT*3];
__device__ float  g_A0 [BATCH*NPTS*64];
__device__ float  g_C0 [BATCH*NPNT*64];
__device__ float  g_x0 [(size_t)BATCH*64 *PIX];
__device__ float  g_x1 [(size_t)BATCH*64 *PIX];
__device__ float  g_max[(size_t)BATCH*128*NPNT];
__device__ float  g_W2d[64*256];                 // W2 pre-duplicated [ci][2*co{dup}]
__device__ double g_sumP[3][128][32];            // 256B-strided accumulators
__device__ double g_sqsP[3][128][32];
__device__ float  g_bna[3][128];
__device__ float  g_bnc[3][128];

// ---------------- mega: fps (blocks 0..15) + a0/zero/dupw2 (blocks 16..271) ----------------
__global__ void __launch_bounds__(256, 1)
mega_kernel(const float* __restrict__ xyz, const float* __restrict__ pts,
            const float* __restrict__ W0, const float* __restrict__ b0,
            const float* __restrict__ W2, float* __restrict__ out)
{
    extern __shared__ float sm[];
    const int t = threadIdx.x;

    if (blockIdx.x < 16) {
        // ===== FPS: EXACT r11/r14 body (measured 273.9us) =====
        float* sx = sm;                              // 4096
        float* sy = sm + NPTS;
        float* sz = sm + 2*NPTS;
        int*   sfi = (int*)(sm + 3*NPTS);            // 1024 selected indices
        __shared__ u64 part[2][8];

        const int b = blockIdx.x;
        const int lane = t & 31, wid = t >> 5;
        const unsigned FULL = 0xffffffffu;
        const float* base = xyz + (size_t)b*3*NPTS;
        for (int n = t; n < NPTS; n += 256) {
            sx[n] = base[n];
            sy[n] = base[NPTS + n];
            sz[n] = base[2*NPTS + n];
        }
        __syncthreads();

        u64 xp[8], yp[8], zp[8];
        #pragma unroll
        for (int j = 0; j < 8; j++) {
            const int p = t + j*256;
            xp[j] = pk2(sx[2*p], sx[2*p+1]);
            yp[j] = pk2(sy[2*p], sy[2*p+1]);
            zp[j] = pk2(sz[2*p], sz[2*p+1]);
        }
        float d[16];
        #pragma unroll
        for (int r = 0; r < 16; r++) d[r] = 1e10f;

        int far = 0;
        for (int i = 0; i < NPNT; i++) {
            const float cx = sx[far], cy = sy[far], cz = sz[far];
            const u64 ncx = pk2(-cx, -cx), ncy = pk2(-cy, -cy), ncz = pk2(-cz, -cz);
            if (t == 0) sfi[i] = far;

            float bv = -1.0f; int bi = 0;
            #pragma unroll
            for (int j = 0; j < 8; j++) {
                const u64 dx = add2(xp[j], ncx);
                const u64 dy = add2(yp[j], ncy);
                const u64 dz = add2(zp[j], ncz);
                const u64 dd = add2(add2(mul2(dx, dx), mul2(dy, dy)), mul2(dz, dz));
                float f0, f1; upk2(dd, f0, f1);
                const int n0 = 2*(t + j*256);
                float& a0r = d[2*j];
                float& a1r = d[2*j + 1];
                a0r = fminf(a0r, f0); if (a0r > bv) { bv = a0r; bi = n0; }
                a1r = fminf(a1r, f1); if (a1r > bv) { bv = a1r; bi = n0 + 1; }
            }
            const unsigned bits = __float_as_uint(bv);
            const unsigned mx   = __reduce_max_sync(FULL, bits);
            const int cand      = (bits == mx) ? bi : 0x7fffffff;
            const int wmin      = __reduce_min_sync(FULL, cand);
            if (lane == 0) part[i & 1][wid] = ((u64)mx << 32) | (unsigned)wmin;
            __syncthreads();
            const u64 v = part[i & 1][lane & 7];
            const unsigned pb = (unsigned)(v >> 32);
            const unsigned m2 = __reduce_max_sync(FULL, pb);
            const int c2 = (pb == m2) ? (int)(unsigned)(v & 0xffffffffu) : 0x7fffffff;
            far = __reduce_min_sync(FULL, c2);
        }
        __syncthreads();
        for (int i = t; i < NPNT; i += 256) {
            const int f = sfi[i];
            const float cx = sx[f], cy = sy[f], cz = sz[f];
            g_new[(b*NPNT + i)*3 + 0] = cx;
            g_new[(b*NPNT + i)*3 + 1] = cy;
            g_new[(b*NPNT + i)*3 + 2] = cz;
            out[b*3*NPNT            + i] = cx;
            out[b*3*NPNT +   NPNT   + i] = cy;
            out[b*3*NPNT + 2*NPNT   + i] = cz;
        }
    } else {
        // ===== a0 (+zero stats, +dupw2 on first a0 block) =====
        const int ab = blockIdx.x - 16;              // [0,256)
        if (ab == 0) {
            for (int i = t; i < 384; i += 256) {     // FIXED: full 384 entries with 256 threads
                const int l = i >> 7, c = i & 127;
                g_sumP[l][c][0] = 0.0;
                g_sqsP[l][c][0] = 0.0;
            }
            for (int i = t; i < 128*64; i += 256) {
                const int co = i >> 6, ci = i & 63;
                const float v = W2[i];
                g_W2d[ci*256 + 2*co]     = v;
                g_W2d[ci*256 + 2*co + 1] = v;
            }
        }
        float* sWt = sm;                             // [j][co] 4288 floats
        float* sB  = sm + CIN0*64;
        const int b = ab >> 4;
        const int n = (ab & 15)*256 + t;
        for (int i = t; i < 64*CIN0; i += 256) {
            const int co = i / CIN0, j = i - co*CIN0;
            sWt[j*64 + co] = W0[i];
        }
        for (int i = t; i < 64; i += 256) sB[i] = b0[i];
        __syncthreads();

        float f[CIN0];
        const float* xb = xyz + (size_t)b*3*NPTS;
        f[0] = xb[n]; f[1] = xb[NPTS + n]; f[2] = xb[2*NPTS + n];
        const float* pb = pts + (size_t)b*64*NPTS;
        #pragma unroll
        for (int j = 0; j < 64; j++) f[3 + j] = pb[(size_t)j*NPTS + n];

        float* outp = g_A0 + ((size_t)b*NPTS + n)*64;
        #pragma unroll 1
        for (int c8 = 0; c8 < 64; c8 += 8) {
            u64 acc[4];
            #pragma unroll
            for (int r = 0; r < 4; r++) acc[r] = pk2(sB[c8 + 2*r], sB[c8 + 2*r + 1]);
            #pragma unroll
            for (int j = 0; j < CIN0; j++) {
                const u64 fd = pk2(f[j], f[j]);
                const ulonglong2 wa = *reinterpret_cast<const ulonglong2*>(sWt + j*64 + c8);
                const ulonglong2 wb = *reinterpret_cast<const ulonglong2*>(sWt + j*64 + c8 + 4);
                ffma2(acc[0], wa.x, fd);
                ffma2(acc[1], wa.y, fd);
                ffma2(acc[2], wb.x, fd);
                ffma2(acc[3], wb.y, fd);
            }
            float v0,v1,v2,v3,v4,v5,v6,v7;
            upk2(acc[0], v0, v1); upk2(acc[1], v2, v3);
            upk2(acc[2], v4, v5); upk2(acc[3], v6, v7);
            *reinterpret_cast<float4*>(outp + c8)     = make_float4(v0, v1, v2, v3);
            *reinterpret_cast<float4*>(outp + c8 + 4) = make_float4(v4, v5, v6, v7);
        }
    }
}

// ---------------- dummy (capture-slot spacer) ----------------
__global__ void dummy_kernel() {}

// ---------------- ball (blocks 0..2047) + c0 (blocks 2048..2111) ----------------
__global__ void __launch_bounds__(256)
ballc0_kernel(const float* __restrict__ xyz, const float* __restrict__ W0)
{
    if (blockIdx.x < 2048) {
        const int w    = (blockIdx.x*256 + threadIdx.x) >> 5;
        const int lane = threadIdx.x & 31;
        const int b = w / NPNT, s = w % NPNT;

        const float cx = g_new[(b*NPNT + s)*3 + 0];
        const float cy = g_new[(b*NPNT + s)*3 + 1];
        const float cz = g_new[(b*NPNT + s)*3 + 2];
        const float ns = cx*cx + cy*cy + cz*cz;
        const float R2 = 0.01f;

        const float* px = xyz + (size_t)b*3*NPTS;
        int cnt = 0, first = 0;
        int* grp = g_grp + (b*NPNT + s)*NSAMP;

        for (int bs = 0; bs < NPTS; bs += 32) {
            const int n = bs + lane;
            const float xx = px[n], xy = px[NPTS + n], xz = px[2*NPTS + n];
            const float dot = cx*xx + cy*xy + cz*xz;
            const float nx  = xx*xx + xy*xy + xz*xz;
            const float d   = -2.0f*dot + ns + nx;
            const bool ok = !(d > R2);
            const unsigned m = __ballot_sync(0xffffffffu, ok);
            if (m) {
                if (cnt == 0) first = bs + __ffs(m) - 1;
                const int pos = cnt + __popc(m & ((1u << lane) - 1u));
                if (ok && pos < NSAMP) grp[pos] = n;
                cnt += __popc(m);
                if (cnt >= NSAMP) break;
            }
        }
        cnt = min(cnt, NSAMP);
        for (int k = cnt + lane; k < NSAMP; k += 32) grp[k] = first;
    } else {
        __shared__ float sw[192];
        const int cb = blockIdx.x - 2048;            // [0,64)
        const int b = cb >> 2;
        const int s = (cb & 3)*256 + threadIdx.x;
        for (int i = threadIdx.x; i < 192; i += 256) sw[i] = W0[(i/3)*CIN0 + (i%3)];
        __syncthreads();

        const float x = g_new[(b*NPNT + s)*3 + 0];
        const float y = g_new[(b*NPNT + s)*3 + 1];
        const float z = g_new[(b*NPNT + s)*3 + 2];
        float* outp = g_C0 + ((size_t)b*NPNT + s)*64;
        #pragma unroll 1
        for (int c4 = 0; c4 < 64; c4 += 4) {
            float4 o;
            o.x = sw[(c4+0)*3]*x + sw[(c4+0)*3+1]*y + sw[(c4+0)*3+2]*z;
            o.y = sw[(c4+1)*3]*x + sw[(c4+1)*3+1]*y + sw[(c4+1)*3+2]*z;
            o.z = sw[(c4+2)*3]*x + sw[(c4+2)*3+1]*y + sw[(c4+2)*3+2]*z;
            o.w = sw[(c4+3)*3]*x + sw[(c4+3)*3+1]*y + sw[(c4+3)*3+2]*z;
            *reinterpret_cast<float4*>(outp + c4) = o;
        }
    }
}

// ---------------- k0s: gather x0 = A0[idx]-C0[s], write + fused BN0 stats ----------------
__global__ void __launch_bounds__(256)
k0s_kernel()
{
    extern __shared__ float smk[];
    float* tile = smk;                            // [64][260]
    int*   sidx = (int*)(smk + 64*260);           // 256 idx
    __shared__ float ps[256], pq[256];

    const int b  = blockIdx.y;
    const int p0 = blockIdx.x * 256;              // 256 pixels, same k
    const int k  = p0 >> 10, s0 = p0 & 1023;
    const int tid = threadIdx.x;

    sidx[tid] = g_grp[(b*NPNT + s0 + tid)*NSAMP + k];
    __syncthreads();

    {
        const int idx = sidx[tid];
        const float4* A = (const float4*)(g_A0 + ((size_t)b*NPTS + idx    )*64);
        const float4* C = (const float4*)(g_C0 + ((size_t)b*NPNT + s0+tid )*64);
        #pragma unroll
        for (int u = 0; u < 16; u++) {
            const float4 a  = A[u];
            const float4 c4 = C[u];
            const int c = u*4;
            tile[(c+0)*260 + tid] = a.x - c4.x;
            tile[(c+1)*260 + tid] = a.y - c4.y;
            tile[(c+2)*260 + tid] = a.z - c4.z;
            tile[(c+3)*260 + tid] = a.w - c4.w;
        }
    }
    __syncthreads();

    {
        float* outb = g_x0 + (size_t)b*64*PIX + p0 + tid;
        #pragma unroll 8
        for (int c = 0; c < 64; c++) outb[(size_t)c*PIX] = tile[c*260 + tid];
    }

    {
        const int c = tid & 63, g = tid >> 6;
        const float* row = tile + c*260 + g*64;
        float s = 0.f, q = 0.f;
        #pragma unroll 16
        for (int j = 0; j < 64; j++) { const float v = row[j]; s += v; q = fmaf(v, v, q); }
        ps[tid] = s; pq[tid] = q;
    }
    __syncthreads();
    if (tid < 64) {
        const float S = ((ps[tid] + ps[tid+64]) + ps[tid+128]) + ps[tid+192];
        const float Q = ((pq[tid] + pq[tid+64]) + pq[tid+128]) + pq[tid+192];
        atomicAdd(&g_sumP[0][tid][0], (double)S);
        atomicAdd(&g_sqsP[0][tid][0], (double)Q);
    }
}

// ---------------- fold BN ----------------
__global__ void finalize_kernel(int layer, int C,
                                const float* __restrict__ gamma,
                                const float* __restrict__ beta)
{
    const int c = threadIdx.x;
    if (c >= C) return;
    const double n = (double)BATCH * PIX;
    const double mean = g_sumP[layer][c][0] / n;
    double var = g_sqsP[layer][c][0] / n - mean*mean;
    if (var < 0.0) var = 0.0;
    const float inv = (float)(1.0 / sqrt(var + 1e-5));
    const float a = gamma[c] * inv;
    g_bna[layer][c] = a;
    g_bnc[layer][c] = beta[c] - (float)mean * a;
}

// ---------------- gemm1 (UNCHANGED from r15) ----------------
__global__ void __launch_bounds__(256)
gemm1_kernel(const float* __restrict__ W, const float* __restrict__ bias)
{
    extern __shared__ float smem[];
    float* Xs = smem;                   // 64 x 256
    float* Wd = Xs + 64*256;            // 64 x 128 (dup pairs per co)
    float* sa = Wd + 64*128;
    float* sc = sa + 64;
    float* sb = sc + 64;

    const int b = blockIdx.y;
    const int pbase = blockIdx.x * 256;
    const int tid = threadIdx.x;

    for (int i = tid; i < 64; i += 256) { sa[i] = g_bna[0][i]; sc[i] = g_bnc[0][i]; sb[i] = bias[i]; }
    for (int i = tid; i < 64*64; i += 256) {
        const int co = i >> 6, ci = i & 63;
        const float v = W[i];
        Wd[ci*128 + 2*co]     = v;
        Wd[ci*128 + 2*co + 1] = v;
    }
    __syncthreads();

    const float* xb = g_x0 + (size_t)b*64*PIX + pbase;
    for (int i = tid; i < 64*256; i += 256) {
        const int ci = i >> 8, pp = i & 255;
        Xs[i] = fmaxf(fmaf(xb[(size_t)ci*PIX + pp], sa[ci], sc[ci]), 0.0f);
    }
    __syncthreads();

    const int p0 = (tid & 31) << 3;
    const int c0 = (tid >> 5) << 3;
    u64 acc[8][4];
    #pragma unroll
    for (int r = 0; r < 8; r++) { acc[r][0]=0ull; acc[r][1]=0ull; acc[r][2]=0ull; acc[r][3]=0ull; }

    #pragma unroll 4
    for (int ci = 0; ci < 64; ci++) {
        const ulonglong2 xa = *reinterpret_cast<const ulonglong2*>(Xs + (ci << 8) + p0);
        const ulonglong2 xc = *reinterpret_cast<const ulonglong2*>(Xs + (ci << 8) + p0 + 4);
        const u64 xq[4] = {xa.x, xa.y, xc.x, xc.y};
        const ulonglong2* wp = reinterpret_cast<const ulonglong2*>(Wd + (ci << 7) + (c0 << 1));
        const ulonglong2 w0 = wp[0], w1 = wp[1], w2 = wp[2], w3 = wp[3];
        const u64 wv[8] = {w0.x, w0.y, w1.x, w1.y, w2.x, w2.y, w3.x, w3.y};
        #pragma unroll
        for (int r = 0; r < 8; r++)
            #pragma unroll
            for (int q = 0; q < 4; q++)
                ffma2(acc[r][q], wv[r], xq[q]);
    }

    float ss[8], qq[8];
    #pragma unroll
    for (int r = 0; r < 8; r++) {
        float v0,v1,v2,v3,v4,v5,v6,v7;
        upk2(acc[r][0], v0, v1); upk2(acc[r][1], v2, v3);
        upk2(acc[r][2], v4, v5); upk2(acc[r][3], v6, v7);
        const float bb = sb[c0 + r];
        v0 += bb; v1 += bb; v2 += bb; v3 += bb;
        v4 += bb; v5 += bb; v6 += bb; v7 += bb;
        float* yb = g_x1 + ((size_t)(b*64 + c0 + r))*PIX + pbase + p0;
        *reinterpret_cast<float4*>(yb)     = make_float4(v0, v1, v2, v3);
        *reinterpret_cast<float4*>(yb + 4) = make_float4(v4, v5, v6, v7);
        ss[r] = (((v0 + v1) + v2) + v3) + (((v4 + v5) + v6) + v7);
        qq[r] = fmaf(v7, v7, fmaf(v6, v6, fmaf(v5, v5, fmaf(v4, v4,
                fmaf(v3, v3, fmaf(v2, v2, fmaf(v1, v1, v0*v0)))))));
    }
    const unsigned FULL = 0xffffffffu;
    #pragma unroll
    for (int r = 0; r < 8; r++) {
        #pragma unroll
        for (int o = 16; o; o >>= 1) {
            ss[r] += __shfl_xor_sync(FULL, ss[r], o);
            qq[r] += __shfl_xor_sync(FULL, qq[r], o);
        }
    }
    if ((tid & 31) == 0) {
        #pragma unroll
        for (int r = 0; r < 8; r++) {
            atomicAdd(&g_sumP[1][c0 + r][0], (double)ss[r]);
            atomicAdd(&g_sqsP[1][c0 + r][0], (double)qq[r]);
        }
    }
}

// ---------------- gemm2 (UNCHANGED from r15) ----------------
__global__ void __launch_bounds__(512)
gemm2_kernel(const float* __restrict__ bias)
{
    extern __shared__ float smem[];
    float* Xs = smem;                   // 4 x (64 x 64)
    float* Wd = Xs + 4*4096;            // 64 x 256 (dup pairs per co)
    float* sa = Wd + 64*256;
    float* sc = sa + 64;
    float* sb = sc + 64;                // 128

    const int b  = blockIdx.y;
    const int s0 = blockIdx.x * 64;
    const int tid = threadIdx.x;

    for (int i = tid; i < 64;  i += 512) { sa[i] = g_bna[1][i]; sc[i] = g_bnc[1][i]; }
    for (int i = tid; i < 128; i += 512) sb[i] = bias[i];
    {
        const float4* src = (const float4*)g_W2d;
        float4* dst = (float4*)Wd;
        for (int i = tid; i < 64*256/4; i += 512) dst[i] = src[i];
    }

    const int pcol = (tid & 15) << 2;
    const int c0   = (tid >> 4) << 2;
    float rmax[4][4];
    float ss[4], qq[4];
    #pragma unroll
    for (int r = 0; r < 4; r++) {
        ss[r] = 0.f; qq[r] = 0.f;
        rmax[r][0] = -3.4e38f; rmax[r][1] = -3.4e38f; rmax[r][2] = -3.4e38f; rmax[r][3] = -3.4e38f;
    }

    const float* xb = g_x1 + (size_t)b*64*PIX + s0;

    for (int ph = 0; ph < NSAMP/4; ph++) {
        __syncthreads();
        #pragma unroll
        for (int kk = 0; kk < 4; kk++) {
            const float* xk = xb + (ph*4 + kk)*NPNT;
            #pragma unroll
            for (int j = 0; j < 8; j++) {
                const int i = tid + j*512;
                const int ci = i >> 6;
                Xs[kk*4096 + i] = fmaxf(fmaf(xk[(size_t)ci*PIX + (i & 63)], sa[ci], sc[ci]), 0.0f);
            }
        }
        __syncthreads();

        u64 acc[4][4][2];
        #pragma unroll
        for (int kk = 0; kk < 4; kk++)
            #pragma unroll
            for (int r = 0; r < 4; r++) { acc[kk][r][0] = 0ull; acc[kk][r][1] = 0ull; }

        #pragma unroll 4
        for (int ci = 0; ci < 64; ci++) {
            const ulonglong2* wp = reinterpret_cast<const ulonglong2*>(Wd + (ci << 8) + (c0 << 1));
            const ulonglong2 w0 = wp[0], w1 = wp[1];
            const u64 wv[4] = {w0.x, w0.y, w1.x, w1.y};
            #pragma unroll
            for (int kk = 0; kk < 4; kk++) {
                const ulonglong2 xv = *reinterpret_cast<const ulonglong2*>(Xs + kk*4096 + (ci << 6) + pcol);
                #pragma unroll
                for (int r = 0; r < 4; r++) {
                    ffma2(acc[kk][r][0], wv[r], xv.x);
                    ffma2(acc[kk][r][1], wv[r], xv.y);
                }
            }
        }

        #pragma unroll
        for (int kk = 0; kk < 4; kk++) {
            #pragma unroll
            for (int r = 0; r < 4; r++) {
                float v0, v1, v2, v3;
                upk2(acc[kk][r][0], v0, v1);
                upk2(acc[kk][r][1], v2, v3);
                const float bb = sb[c0 + r];
                v0 += bb; v1 += bb; v2 += bb; v3 += bb;
                rmax[r][0] = fmaxf(rmax[r][0], v0);
                rmax[r][1] = fmaxf(rmax[r][1], v1);
                rmax[r][2] = fmaxf(rmax[r][2], v2);
                rmax[r][3] = fmaxf(rmax[r][3], v3);
                ss[r] += v0; qq[r] = fmaf(v0, v0, qq[r]);
                ss[r] += v1; qq[r] = fmaf(v1, v1, qq[r]);
                ss[r] += v2; qq[r] = fmaf(v2, v2, qq[r]);
                ss[r] += v3; qq[r] = fmaf(v3, v3, qq[r]);
            }
        }
    }

    #pragma unroll
    for (int r = 0; r < 4; r++) {
        *reinterpret_cast<float4*>(g_max + (((size_t)(b*128 + c0 + r)) << 10) + s0 + pcol)
            = make_float4(rmax[r][0], rmax[r][1], rmax[r][2], rmax[r][3]);
    }
    const unsigned FULL = 0xffffffffu;
    #pragma unroll
    for (int r = 0; r < 4; r++) {
        #pragma unroll
        for (int o = 8; o; o >>= 1) {
            ss[r] += __shfl_xor_sync(FULL, ss[r], o);
            qq[r] += __shfl_xor_sync(FULL, qq[r], o);
        }
    }
    if ((tid & 15) == 0) {
        #pragma unroll
        for (int r = 0; r < 4; r++) {
            atomicAdd(&g_sumP[2][c0 + r][0], (double)ss[r]);
            atomicAdd(&g_sqsP[2][c0 + r][0], (double)qq[r]);
        }
    }
}

// ---------------- apply BN2+relu to the raw max ----------------
__global__ void __launch_bounds__(256)
maxapply_kernel(float* __restrict__ out)
{
    const int idx = blockIdx.x*256 + threadIdx.x;
    const int co  = (idx >> 10) & 127;
    const float v = g_max[idx];
    out[BATCH*3*NPNT + idx] = fmaxf(fmaf(v, g_bna[2][co], g_bnc[2][co]), 0.0f);
}

// ---------------- launcher ----------------
extern "C" void kernel_launch(void* const* d_in, const int* in_sizes, int n_in,
                              void* d_out, int out_size)
{
    const float* xyz = (const float*)d_in[0];
    const float* pts = (const float*)d_in[1];
    const float* W0  = (const float*)d_in[2];
    const float* b0  = (const float*)d_in[3];
    const float* ga0 = (const float*)d_in[4];
    const float* be0 = (const float*)d_in[5];
    const float* W1  = (const float*)d_in[6];
    const float* b1  = (const float*)d_in[7];
    const float* ga1 = (const float*)d_in[8];
    const float* be1 = (const float*)d_in[9];
    const float* W2  = (const float*)d_in[10];
    const float* b2  = (const float*)d_in[11];
    const float* ga2 = (const float*)d_in[12];
    const float* be2 = (const float*)d_in[13];
    float* out = (float*)d_out;

    const int MEGA_SMEM = (3*NPTS)*4 + NPNT*4;             // 53,248 (fps layout; a0 uses a prefix)
    const int K0_SMEM  = (64*260)*4 + 256*4;               // 67,584
    const int SM1 = (64*256 + 64*128 + 64+64+64 ) * 4;     // 99,072
    const int SM2 = (4*4096 + 64*256 + 64+64+128) * 4;     // 132,096
    cudaFuncSetAttribute((const void*)mega_kernel,  cudaFuncAttributeMaxDynamicSharedMemorySize, MEGA_SMEM);
    cudaFuncSetAttribute((const void*)k0s_kernel,   cudaFuncAttributeMaxDynamicSharedMemorySize, K0_SMEM);
    cudaFuncSetAttribute((const void*)gemm1_kernel, cudaFuncAttributeMaxDynamicSharedMemorySize, SM1);
    cudaFuncSetAttribute((const void*)gemm2_kernel, cudaFuncAttributeMaxDynamicSharedMemorySize, SM2);

    // launch order: capture slot (#4) lands on k0s this round
    mega_kernel  <<<16 + 256, 256, MEGA_SMEM>>>(xyz, pts, W0, b0, W2, out);
    dummy_kernel <<<1, 32>>>();
    ballc0_kernel<<<2048 + 64, 256>>>(xyz, W0);
    k0s_kernel   <<<dim3(PIX/256, BATCH), 256, K0_SMEM>>>();

    finalize_kernel<<<1, 128>>>(0, 64, ga0, be0);
    gemm1_kernel   <<<dim3(PIX/256, BATCH), 256, SM1>>>(W1, b1);

    finalize_kernel<<<1, 128>>>(1, 64, ga1, be1);
    gemm2_kernel   <<<dim3(NPNT/64, BATCH), 512, SM2>>>(b2);

    finalize_kernel<<<1, 128>>>(2, 128, ga2, be2);
    maxapply_kernel<<<(BATCH*128*NPNT)/256, 256>>>(out);
}